// round 1
// baseline (speedup 1.0000x reference)
#include <cuda_runtime.h>
#include <math.h>

// ---------------- problem constants ----------------
constexpr int kB = 16;
constexpr int kS = 512;
constexpr int kD = 512;
constexpr int kH = 8;
constexpr int kDPH = 64;     // D / H
constexpr int kL = 6;
constexpr int kDFF = 2048;
constexpr int kVOCAB = 1024;
constexpr int kNPC = 4096;
constexpr int kNS = 4096;
constexpr int kM = kB * kS;  // 8192 rows

// ---------------- scratch (static device globals; no allocations) ----------------
__device__ float g_x[(size_t)kM * kD];
__device__ float g_q[(size_t)kM * kD];
__device__ float g_k[(size_t)kM * kD];
__device__ float g_v[(size_t)kM * kD];
__device__ float g_o[(size_t)kM * kD];
__device__ float g_t[(size_t)kM * kD];
__device__ float g_ff[(size_t)kM * kDFF];
__device__ float g_scores[(size_t)kB * kH * kS * kS];

// ---------------- embedding + positional + degree ----------------
__global__ __launch_bounds__(128) void embed_kernel(
    const int* __restrict__ raw_x, const int* __restrict__ deg,
    const float* __restrict__ vemb, const float* __restrict__ demb,
    float* __restrict__ x)
{
    const int row = blockIdx.x;          // b*S + s
    const int s = row & (kS - 1);
    const int tok = raw_x[row];
    const int dg = deg[row];
    const float c0 = -logf(10000.0f) / (float)kD;
    for (int c = threadIdx.x; c < kD; c += blockDim.x) {
        int p = c >> 1;
        float ang = (float)s * expf((float)(2 * p) * c0);
        float pe = (c & 1) ? cosf(ang) : sinf(ang);
        x[(size_t)row * kD + c] = vemb[(size_t)tok * kD + c] + pe + demb[(size_t)dg * kD + c];
    }
}

// ---------------- active-relation "now" adds ----------------
__global__ __launch_bounds__(256) void relnow_kernel(
    const int* __restrict__ pcn, const int* __restrict__ sn,
    const float* __restrict__ are, float* __restrict__ x)
{
    int idx = blockIdx.x * blockDim.x + threadIdx.x;   // B*D threads
    if (idx >= kB * kD) return;
    int b = idx / kD, c = idx % kD;
    {
        int bb = pcn[b * 2 + 0], ss = pcn[b * 2 + 1];
        atomicAdd(&x[((size_t)bb * kS + ss) * kD + c], are[c]);
    }
    {
        int bb = sn[b * 2 + 0], ss = sn[b * 2 + 1];
        atomicAdd(&x[((size_t)bb * kS + ss) * kD + c], are[kD + c]);
    }
}

// ---------------- generic GEMM: C[M,N] = A[M,K] @ W[N,K]^T + bias (+relu) ----------------
template <bool RELU>
__global__ __launch_bounds__(256) void gemm_bt_kernel(
    const float* __restrict__ A, const float* __restrict__ W,
    const float* __restrict__ bias, float* __restrict__ C,
    int M, int N, int K)
{
    __shared__ float As[16][64];
    __shared__ float Ws[16][64];
    const int tid = threadIdx.x;
    const int tx = tid & 15, ty = tid >> 4;
    const int m0 = blockIdx.y << 6;
    const int n0 = blockIdx.x << 6;
    const int lr = tid >> 2;
    const int lc = (tid & 3) << 2;
    const float* Ap = A + (size_t)(m0 + lr) * K + lc;
    const float* Wp = W + (size_t)(n0 + lr) * K + lc;
    float acc[4][4] = {};
    for (int k0 = 0; k0 < K; k0 += 16) {
        float4 a = *(const float4*)(Ap + k0);
        float4 w = *(const float4*)(Wp + k0);
        As[lc + 0][lr] = a.x; As[lc + 1][lr] = a.y; As[lc + 2][lr] = a.z; As[lc + 3][lr] = a.w;
        Ws[lc + 0][lr] = w.x; Ws[lc + 1][lr] = w.y; Ws[lc + 2][lr] = w.z; Ws[lc + 3][lr] = w.w;
        __syncthreads();
#pragma unroll
        for (int kk = 0; kk < 16; kk++) {
            float4 ar4 = *(const float4*)&As[kk][ty << 2];
            float4 wr4 = *(const float4*)&Ws[kk][tx << 2];
            float av[4] = {ar4.x, ar4.y, ar4.z, ar4.w};
            float wv[4] = {wr4.x, wr4.y, wr4.z, wr4.w};
#pragma unroll
            for (int i = 0; i < 4; i++)
#pragma unroll
                for (int j = 0; j < 4; j++)
                    acc[i][j] += av[i] * wv[j];
        }
        __syncthreads();
    }
    float4 b4 = *(const float4*)(bias + n0 + (tx << 2));
    float bv[4] = {b4.x, b4.y, b4.z, b4.w};
#pragma unroll
    for (int i = 0; i < 4; i++) {
        float4 outv;
        float* ov = (float*)&outv;
#pragma unroll
        for (int j = 0; j < 4; j++) {
            float val = acc[i][j] + bv[j];
            if (RELU) val = fmaxf(val, 0.0f);
            ov[j] = val;
        }
        *(float4*)(C + (size_t)(m0 + (ty << 2) + i) * N + n0 + (tx << 2)) = outv;
    }
}

// ---------------- scores: per (b,h)  S[i,j] = (Q_i . K_j) / sqrt(DPH) ----------------
__global__ __launch_bounds__(256) void scores_kernel(
    const float* __restrict__ q, const float* __restrict__ k,
    float* __restrict__ scores)
{
    const int bh = blockIdx.z;
    const int b = bh >> 3, h = bh & 7;
    const float* Qb = q + (size_t)b * kS * kD + h * kDPH;
    const float* Kb = k + (size_t)b * kS * kD + h * kDPH;
    const int i0 = blockIdx.y << 6, j0 = blockIdx.x << 6;
    __shared__ float As[16][64];
    __shared__ float Bs[16][64];
    const int tid = threadIdx.x;
    const int tx = tid & 15, ty = tid >> 4;
    const int lr = tid >> 2;
    const int lc = (tid & 3) << 2;
    float acc[4][4] = {};
    for (int k0 = 0; k0 < kDPH; k0 += 16) {
        float4 a = *(const float4*)(Qb + (size_t)(i0 + lr) * kD + k0 + lc);
        float4 bb = *(const float4*)(Kb + (size_t)(j0 + lr) * kD + k0 + lc);
        As[lc + 0][lr] = a.x;  As[lc + 1][lr] = a.y;  As[lc + 2][lr] = a.z;  As[lc + 3][lr] = a.w;
        Bs[lc + 0][lr] = bb.x; Bs[lc + 1][lr] = bb.y; Bs[lc + 2][lr] = bb.z; Bs[lc + 3][lr] = bb.w;
        __syncthreads();
#pragma unroll
        for (int kk = 0; kk < 16; kk++) {
            float4 ar4 = *(const float4*)&As[kk][ty << 2];
            float4 br4 = *(const float4*)&Bs[kk][tx << 2];
            float av[4] = {ar4.x, ar4.y, ar4.z, ar4.w};
            float bv[4] = {br4.x, br4.y, br4.z, br4.w};
#pragma unroll
            for (int i = 0; i < 4; i++)
#pragma unroll
                for (int j = 0; j < 4; j++)
                    acc[i][j] += av[i] * bv[j];
        }
        __syncthreads();
    }
    const float inv = 0.125f; // 1/sqrt(64)
#pragma unroll
    for (int i = 0; i < 4; i++) {
        float4 outv;
        float* ov = (float*)&outv;
#pragma unroll
        for (int j = 0; j < 4; j++) ov[j] = acc[i][j] * inv;
        *(float4*)(scores + ((size_t)bh * kS + i0 + (ty << 2) + i) * kS + j0 + (tx << 2)) = outv;
    }
}

// ---------------- relation bias scatters into scores ----------------
__global__ __launch_bounds__(256) void relbias_pc_kernel(
    const int* __restrict__ pci, const float* __restrict__ rel,
    float* __restrict__ scores)
{
    int idx = blockIdx.x * blockDim.x + threadIdx.x;
    if (idx >= kNPC * kH) return;
    int e = idx >> 3, h = idx & 7;
    int b = pci[e * 3 + 0], i = pci[e * 3 + 1], j = pci[e * 3 + 2];
    size_t base = (size_t)(b * kH + h) * kS;
    atomicAdd(&scores[(base + i) * kS + j], rel[0]);
    atomicAdd(&scores[(base + j) * kS + i], rel[1]);
}

__global__ __launch_bounds__(256) void relbias_sib_kernel(
    const int* __restrict__ sbi, const float* __restrict__ rel,
    float* __restrict__ scores)
{
    int idx = blockIdx.x * blockDim.x + threadIdx.x;
    if (idx >= kNS * kH) return;
    int e = idx >> 3, h = idx & 7;
    int b = sbi[e * 3 + 0], i = sbi[e * 3 + 1], j = sbi[e * 3 + 2];
    size_t base = (size_t)(b * kH + h) * kS;
    float r2 = rel[2];
    atomicAdd(&scores[(base + i) * kS + j], r2);
    atomicAdd(&scores[(base + j) * kS + i], r2);
}

// ---------------- softmax over last dim (row length 512), warp per row ----------------
__global__ __launch_bounds__(256) void softmax_kernel(float* __restrict__ sc)
{
    const size_t row = (size_t)blockIdx.x * 8 + (threadIdx.x >> 5);
    const int lane = threadIdx.x & 31;
    float* p = sc + row * kS;
    float v[16];
    float mx = -1e30f;
#pragma unroll
    for (int t = 0; t < 16; t++) { v[t] = p[lane + t * 32]; mx = fmaxf(mx, v[t]); }
#pragma unroll
    for (int s = 16; s; s >>= 1) mx = fmaxf(mx, __shfl_xor_sync(0xffffffffu, mx, s));
    float sum = 0.0f;
#pragma unroll
    for (int t = 0; t < 16; t++) { v[t] = expf(v[t] - mx); sum += v[t]; }
#pragma unroll
    for (int s = 16; s; s >>= 1) sum += __shfl_xor_sync(0xffffffffu, sum, s);
    float inv = 1.0f / sum;
#pragma unroll
    for (int t = 0; t < 16; t++) p[lane + t * 32] = v[t] * inv;
}

// ---------------- O = attn @ V per (b,h) ----------------
__global__ __launch_bounds__(256) void av_kernel(
    const float* __restrict__ P, const float* __restrict__ v,
    float* __restrict__ o)
{
    const int bh = blockIdx.y;
    const int b = bh >> 3, h = bh & 7;
    const int i0 = blockIdx.x << 6;
    const float* Pb = P + (size_t)bh * kS * kS;
    const float* Vb = v + (size_t)b * kS * kD + h * kDPH;
    __shared__ float Ps[16][64];   // [j][i]
    __shared__ float Vs[16][64];   // [j][d]
    const int tid = threadIdx.x;
    const int tx = tid & 15, ty = tid >> 4;
    const int lr = tid >> 2;           // i within tile for P load
    const int lc = (tid & 3) << 2;     // j offset within tile for P load
    const int vr = tid >> 4;           // j within tile for V load (0..15)
    const int vc = (tid & 15) << 2;    // d offset for V load
    float acc[4][4] = {};
    for (int j0 = 0; j0 < kS; j0 += 16) {
        float4 p4 = *(const float4*)(Pb + (size_t)(i0 + lr) * kS + j0 + lc);
        Ps[lc + 0][lr] = p4.x; Ps[lc + 1][lr] = p4.y; Ps[lc + 2][lr] = p4.z; Ps[lc + 3][lr] = p4.w;
        float4 v4 = *(const float4*)(Vb + (size_t)(j0 + vr) * kD + vc);
        *(float4*)&Vs[vr][vc] = v4;
        __syncthreads();
#pragma unroll
        for (int jj = 0; jj < 16; jj++) {
            float4 ar4 = *(const float4*)&Ps[jj][ty << 2];
            float4 vr4 = *(const float4*)&Vs[jj][tx << 2];
            float av[4] = {ar4.x, ar4.y, ar4.z, ar4.w};
            float vv[4] = {vr4.x, vr4.y, vr4.z, vr4.w};
#pragma unroll
            for (int i = 0; i < 4; i++)
#pragma unroll
                for (int j = 0; j < 4; j++)
                    acc[i][j] += av[i] * vv[j];
        }
        __syncthreads();
    }
#pragma unroll
    for (int i = 0; i < 4; i++) {
        float4 outv;
        float* ov = (float*)&outv;
#pragma unroll
        for (int j = 0; j < 4; j++) ov[j] = acc[i][j];
        *(float4*)(o + (size_t)(b * kS + i0 + (ty << 2) + i) * kD + h * kDPH + (tx << 2)) = outv;
    }
}

// ---------------- LN(a + r), warp per row ----------------
__global__ __launch_bounds__(256) void ln_residual_kernel(
    const float* __restrict__ a, const float* __restrict__ r,
    const float* __restrict__ g, const float* __restrict__ bet,
    float* __restrict__ out)
{
    const size_t row = (size_t)blockIdx.x * 8 + (threadIdx.x >> 5);
    const int lane = threadIdx.x & 31;
    const float* ap = a + row * kD;
    const float* rp = r + row * kD;
    float v[16];
    float sum = 0.0f;
#pragma unroll
    for (int t = 0; t < 16; t++) {
        v[t] = ap[lane + t * 32] + rp[lane + t * 32];
        sum += v[t];
    }
#pragma unroll
    for (int s = 16; s; s >>= 1) sum += __shfl_xor_sync(0xffffffffu, sum, s);
    float mean = sum * (1.0f / kD);
    float s2 = 0.0f;
#pragma unroll
    for (int t = 0; t < 16; t++) { float d = v[t] - mean; s2 += d * d; }
#pragma unroll
    for (int s = 16; s; s >>= 1) s2 += __shfl_xor_sync(0xffffffffu, s2, s);
    float rstd = rsqrtf(s2 * (1.0f / kD) + 1e-5f);
#pragma unroll
    for (int t = 0; t < 16; t++) {
        int c = lane + t * 32;
        out[row * kD + c] = (v[t] - mean) * rstd * g[c] + bet[c];
    }
}

// ---------------- final logits: out[b, vcb] = x[b, S-1] . logits_w[vcb] ----------------
__global__ __launch_bounds__(256) void logits_kernel(
    const float* __restrict__ x, const float* __restrict__ w,
    float* __restrict__ out)
{
    int gw = (blockIdx.x * blockDim.x + threadIdx.x) >> 5;  // global warp = output index
    int lane = threadIdx.x & 31;
    if (gw >= kB * kVOCAB) return;
    int b = gw >> 10;
    int vcb = gw & (kVOCAB - 1);
    const float* xr = x + ((size_t)b * kS + (kS - 1)) * kD;
    const float* wr = w + (size_t)vcb * kD;
    float s = 0.0f;
#pragma unroll
    for (int t = 0; t < 16; t++) s += xr[lane + t * 32] * wr[lane + t * 32];
#pragma unroll
    for (int sh = 16; sh; sh >>= 1) s += __shfl_xor_sync(0xffffffffu, s, sh);
    if (lane == 0) out[gw] = s;
}

// ---------------- host launcher ----------------
extern "C" void kernel_launch(void* const* d_in, const int* in_sizes, int n_in,
                              void* d_out, int out_size)
{
    (void)in_sizes; (void)n_in; (void)out_size;
    const int*   raw_x = (const int*)d_in[0];
    const int*   deg   = (const int*)d_in[1];
    const int*   pci   = (const int*)d_in[2];
    const int*   pcn   = (const int*)d_in[3];
    const int*   sbi   = (const int*)d_in[4];
    const int*   sbn   = (const int*)d_in[5];
    const float* vemb  = (const float*)d_in[6];
    const float* demb  = (const float*)d_in[7];
    const float* are   = (const float*)d_in[8];
    const float* rel   = (const float*)d_in[9];
    const float* Wq    = (const float*)d_in[10];
    const float* bq    = (const float*)d_in[11];
    const float* Wk    = (const float*)d_in[12];
    const float* bk    = (const float*)d_in[13];
    const float* Wv    = (const float*)d_in[14];
    const float* bv    = (const float*)d_in[15];
    const float* Wo    = (const float*)d_in[16];
    const float* bo    = (const float*)d_in[17];
    const float* W1    = (const float*)d_in[18];
    const float* b1    = (const float*)d_in[19];
    const float* W2    = (const float*)d_in[20];
    const float* b2    = (const float*)d_in[21];
    const float* lng   = (const float*)d_in[22];
    const float* lnb   = (const float*)d_in[23];
    const float* logw  = (const float*)d_in[24];
    float* out = (float*)d_out;

    float *x, *q, *k, *v, *o, *t, *ff, *sc;
    cudaGetSymbolAddress((void**)&x,  g_x);
    cudaGetSymbolAddress((void**)&q,  g_q);
    cudaGetSymbolAddress((void**)&k,  g_k);
    cudaGetSymbolAddress((void**)&v,  g_v);
    cudaGetSymbolAddress((void**)&o,  g_o);
    cudaGetSymbolAddress((void**)&t,  g_t);
    cudaGetSymbolAddress((void**)&ff, g_ff);
    cudaGetSymbolAddress((void**)&sc, g_scores);

    embed_kernel<<<kM, 128>>>(raw_x, deg, vemb, demb, x);
    relnow_kernel<<<(kB * kD + 255) / 256, 256>>>(pcn, sbn, are, x);

    const dim3 gD(kD / 64, kM / 64);       // N=512 GEMMs
    const dim3 gFF(kDFF / 64, kM / 64);    // N=2048 GEMM
    const dim3 gSc(kS / 64, kS / 64, kB * kH);
    const dim3 gAv(kS / 64, kB * kH);

    for (int l = 0; l < kL; l++) {
        const float* wq = Wq + (size_t)l * kD * kD;
        const float* wk = Wk + (size_t)l * kD * kD;
        const float* wv = Wv + (size_t)l * kD * kD;
        const float* wo = Wo + (size_t)l * kD * kD;
        const float* w1 = W1 + (size_t)l * kDFF * kD;
        const float* w2 = W2 + (size_t)l * kD * kDFF;
        const float* bql = bq + (size_t)l * kD;
        const float* bkl = bk + (size_t)l * kD;
        const float* bvl = bv + (size_t)l * kD;
        const float* bol = bo + (size_t)l * kD;
        const float* b1l = b1 + (size_t)l * kDFF;
        const float* b2l = b2 + (size_t)l * kD;
        const float* lngl = lng + (size_t)l * kD;
        const float* lnbl = lnb + (size_t)l * kD;

        gemm_bt_kernel<false><<<gD, 256>>>(x, wq, bql, q, kM, kD, kD);
        gemm_bt_kernel<false><<<gD, 256>>>(x, wk, bkl, k, kM, kD, kD);
        gemm_bt_kernel<false><<<gD, 256>>>(x, wv, bvl, v, kM, kD, kD);

        scores_kernel<<<gSc, 256>>>(q, k, sc);
        relbias_pc_kernel<<<(kNPC * kH + 255) / 256, 256>>>(pci, rel, sc);
        relbias_sib_kernel<<<(kNS * kH + 255) / 256, 256>>>(sbi, rel, sc);
        softmax_kernel<<<(kB * kH * kS) / 8, 256>>>(sc);
        av_kernel<<<gAv, 256>>>(sc, v, o);

        gemm_bt_kernel<false><<<gD, 256>>>(o, wo, bol, t, kM, kD, kD);
        ln_residual_kernel<<<kM / 8, 256>>>(x, t, lngl, lnbl, x);

        gemm_bt_kernel<true><<<gFF, 256>>>(x, w1, b1l, ff, kM, kDFF, kD);
        gemm_bt_kernel<false><<<gD, 256>>>(ff, w2, b2l, t, kM, kD, kDFF);
        ln_residual_kernel<<<kM / 8, 256>>>(x, t, lngl, lnbl, x);
    }

    logits_kernel<<<(kB * kVOCAB * 32 + 255) / 256, 256>>>(x, logw, out);
}

// round 2
// speedup vs baseline: 3.1224x; 3.1224x over previous
#include <cuda_runtime.h>
#include <math.h>
#include <stdint.h>

// ---------------- problem constants ----------------
constexpr int kB = 16;
constexpr int kS = 512;
constexpr int kD = 512;
constexpr int kH = 8;
constexpr int kDPH = 64;     // D / H
constexpr int kL = 6;
constexpr int kDFF = 2048;
constexpr int kVOCAB = 1024;
constexpr int kNPC = 4096;
constexpr int kNS = 4096;
constexpr int kM = kB * kS;  // 8192 rows

// ---------------- scratch (static device globals; no allocations) ----------------
__device__ float g_x[(size_t)kM * kD];
__device__ float g_q[(size_t)kM * kD];
__device__ float g_k[(size_t)kM * kD];
__device__ float g_v[(size_t)kM * kD];
__device__ float g_o[(size_t)kM * kD];
__device__ float g_t[(size_t)kM * kD];
__device__ float g_ff[(size_t)kM * kDFF];
__device__ float g_scores[(size_t)kB * kH * kS * kS];

// ---------------- tf32 helpers ----------------
__device__ __forceinline__ uint32_t f2tf(float f) {
    uint32_t u;
    asm("cvt.rna.tf32.f32 %0, %1;" : "=r"(u) : "f"(f));
    return u;
}

__device__ __forceinline__ void mma8(float* c, const uint32_t* a, const uint32_t* b) {
    asm volatile(
        "mma.sync.aligned.m16n8k8.row.col.f32.tf32.tf32.f32 "
        "{%0,%1,%2,%3},{%4,%5,%6,%7},{%8,%9},{%0,%1,%2,%3};"
        : "+f"(c[0]), "+f"(c[1]), "+f"(c[2]), "+f"(c[3])
        : "r"(a[0]), "r"(a[1]), "r"(a[2]), "r"(a[3]), "r"(b[0]), "r"(b[1]));
}

// ---------------- embedding + positional + degree ----------------
__global__ __launch_bounds__(128) void embed_kernel(
    const int* __restrict__ raw_x, const int* __restrict__ deg,
    const float* __restrict__ vemb, const float* __restrict__ demb,
    float* __restrict__ x)
{
    const int row = blockIdx.x;          // b*S + s
    const int s = row & (kS - 1);
    const int tok = raw_x[row];
    const int dg = deg[row];
    const float c0 = -logf(10000.0f) / (float)kD;
    for (int c = threadIdx.x; c < kD; c += blockDim.x) {
        int p = c >> 1;
        float ang = (float)s * expf((float)(2 * p) * c0);
        float pe = (c & 1) ? cosf(ang) : sinf(ang);
        x[(size_t)row * kD + c] = vemb[(size_t)tok * kD + c] + pe + demb[(size_t)dg * kD + c];
    }
}

// ---------------- active-relation "now" adds ----------------
__global__ __launch_bounds__(256) void relnow_kernel(
    const int* __restrict__ pcn, const int* __restrict__ sn,
    const float* __restrict__ are, float* __restrict__ x)
{
    int idx = blockIdx.x * blockDim.x + threadIdx.x;   // B*D threads
    if (idx >= kB * kD) return;
    int b = idx / kD, c = idx % kD;
    {
        int bb = pcn[b * 2 + 0], ss = pcn[b * 2 + 1];
        atomicAdd(&x[((size_t)bb * kS + ss) * kD + c], are[c]);
    }
    {
        int bb = sn[b * 2 + 0], ss = sn[b * 2 + 1];
        atomicAdd(&x[((size_t)bb * kS + ss) * kD + c], are[kD + c]);
    }
}

// ============================================================
// Generic tensor-core GEMM: C[M,N] = A[M,K] @ W[N,K]^T + bias (+relu)
// 128x128 block tile, 8 warps (64x32 warp tiles), BK=32, tf32 mma.
// smem stride 36 (== 4 mod 32): conflict-free STS.128 and fragment LDS.
// ============================================================
template <bool RELU>
__global__ __launch_bounds__(256, 1) void gemm_tc(
    const float* __restrict__ A, const float* __restrict__ W,
    const float* __restrict__ bias, float* __restrict__ C,
    int M, int N, int K)
{
    __shared__ uint32_t As[128][36];
    __shared__ uint32_t Bs[128][36];
    const int tid = threadIdx.x;
    const int lane = tid & 31, warp = tid >> 5;
    const int wm = warp >> 2, wn = warp & 3;
    const int m0 = blockIdx.y << 7, n0 = blockIdx.x << 7;

    float4 pa[4], pb[4];
#pragma unroll
    for (int it = 0; it < 4; it++) {
        int idx = tid + (it << 8);
        int row = idx >> 3, kq = (idx & 7) << 2;
        pa[it] = *(const float4*)(A + (size_t)(m0 + row) * K + kq);
        pb[it] = *(const float4*)(W + (size_t)(n0 + row) * K + kq);
    }
    float acc[4][4][4] = {};
    const int nchunks = K >> 5;
    for (int ch = 0; ch < nchunks; ch++) {
#pragma unroll
        for (int it = 0; it < 4; it++) {
            int idx = tid + (it << 8);
            int row = idx >> 3, kq = (idx & 7) << 2;
            As[row][kq + 0] = f2tf(pa[it].x); As[row][kq + 1] = f2tf(pa[it].y);
            As[row][kq + 2] = f2tf(pa[it].z); As[row][kq + 3] = f2tf(pa[it].w);
            Bs[row][kq + 0] = f2tf(pb[it].x); Bs[row][kq + 1] = f2tf(pb[it].y);
            Bs[row][kq + 2] = f2tf(pb[it].z); Bs[row][kq + 3] = f2tf(pb[it].w);
        }
        __syncthreads();
        if (ch + 1 < nchunks) {
            int k0 = (ch + 1) << 5;
#pragma unroll
            for (int it = 0; it < 4; it++) {
                int idx = tid + (it << 8);
                int row = idx >> 3, kq = (idx & 7) << 2;
                pa[it] = *(const float4*)(A + (size_t)(m0 + row) * K + k0 + kq);
                pb[it] = *(const float4*)(W + (size_t)(n0 + row) * K + k0 + kq);
            }
        }
#pragma unroll
        for (int kk = 0; kk < 32; kk += 8) {
            uint32_t af[4][4], bf[4][2];
#pragma unroll
            for (int mt = 0; mt < 4; mt++) {
                int r = (wm << 6) + (mt << 4) + (lane >> 2);
                int kc = kk + (lane & 3);
                af[mt][0] = As[r][kc];
                af[mt][1] = As[r + 8][kc];
                af[mt][2] = As[r][kc + 4];
                af[mt][3] = As[r + 8][kc + 4];
            }
#pragma unroll
            for (int nt = 0; nt < 4; nt++) {
                int cidx = (wn << 5) + (nt << 3) + (lane >> 2);
                int kc = kk + (lane & 3);
                bf[nt][0] = Bs[cidx][kc];
                bf[nt][1] = Bs[cidx][kc + 4];
            }
#pragma unroll
            for (int mt = 0; mt < 4; mt++)
#pragma unroll
                for (int nt = 0; nt < 4; nt++)
                    mma8(acc[mt][nt], af[mt], bf[nt]);
        }
        __syncthreads();
    }
#pragma unroll
    for (int mt = 0; mt < 4; mt++) {
        int row = m0 + (wm << 6) + (mt << 4) + (lane >> 2);
#pragma unroll
        for (int nt = 0; nt < 4; nt++) {
            int col = n0 + (wn << 5) + (nt << 3) + ((lane & 3) << 1);
            float bb0 = bias[col], bb1 = bias[col + 1];
            float v0 = acc[mt][nt][0] + bb0, v1 = acc[mt][nt][1] + bb1;
            float v2 = acc[mt][nt][2] + bb0, v3 = acc[mt][nt][3] + bb1;
            if (RELU) {
                v0 = fmaxf(v0, 0.0f); v1 = fmaxf(v1, 0.0f);
                v2 = fmaxf(v2, 0.0f); v3 = fmaxf(v3, 0.0f);
            }
            *(float2*)(C + (size_t)row * N + col) = make_float2(v0, v1);
            *(float2*)(C + (size_t)(row + 8) * N + col) = make_float2(v2, v3);
        }
    }
}

// ============================================================
// Scores: per (b,h)  S[i,j] = (Q_i . K_j) / 8   — tf32 mma, K=64
// ============================================================
__global__ __launch_bounds__(256, 1) void scores_tc(
    const float* __restrict__ q, const float* __restrict__ k,
    float* __restrict__ scores)
{
    __shared__ uint32_t As[128][36];
    __shared__ uint32_t Bs[128][36];
    const int bh = blockIdx.z;
    const int b = bh >> 3, h = bh & 7;
    const float* Qb = q + (size_t)b * kS * kD + h * kDPH;
    const float* Kb = k + (size_t)b * kS * kD + h * kDPH;
    const int i0 = blockIdx.y << 7, j0 = blockIdx.x << 7;
    const int tid = threadIdx.x;
    const int lane = tid & 31, warp = tid >> 5;
    const int wm = warp >> 2, wn = warp & 3;

    float acc[4][4][4] = {};
#pragma unroll
    for (int ch = 0; ch < 2; ch++) {
        int k0 = ch << 5;
#pragma unroll
        for (int it = 0; it < 4; it++) {
            int idx = tid + (it << 8);
            int row = idx >> 3, kq = (idx & 7) << 2;
            float4 a = *(const float4*)(Qb + (size_t)(i0 + row) * kD + k0 + kq);
            float4 bb = *(const float4*)(Kb + (size_t)(j0 + row) * kD + k0 + kq);
            As[row][kq + 0] = f2tf(a.x);  As[row][kq + 1] = f2tf(a.y);
            As[row][kq + 2] = f2tf(a.z);  As[row][kq + 3] = f2tf(a.w);
            Bs[row][kq + 0] = f2tf(bb.x); Bs[row][kq + 1] = f2tf(bb.y);
            Bs[row][kq + 2] = f2tf(bb.z); Bs[row][kq + 3] = f2tf(bb.w);
        }
        __syncthreads();
#pragma unroll
        for (int kk = 0; kk < 32; kk += 8) {
            uint32_t af[4][4], bf[4][2];
#pragma unroll
            for (int mt = 0; mt < 4; mt++) {
                int r = (wm << 6) + (mt << 4) + (lane >> 2);
                int kc = kk + (lane & 3);
                af[mt][0] = As[r][kc];
                af[mt][1] = As[r + 8][kc];
                af[mt][2] = As[r][kc + 4];
                af[mt][3] = As[r + 8][kc + 4];
            }
#pragma unroll
            for (int nt = 0; nt < 4; nt++) {
                int cidx = (wn << 5) + (nt << 3) + (lane >> 2);
                int kc = kk + (lane & 3);
                bf[nt][0] = Bs[cidx][kc];
                bf[nt][1] = Bs[cidx][kc + 4];
            }
#pragma unroll
            for (int mt = 0; mt < 4; mt++)
#pragma unroll
                for (int nt = 0; nt < 4; nt++)
                    mma8(acc[mt][nt], af[mt], bf[nt]);
        }
        __syncthreads();
    }
    float* Cb = scores + (size_t)bh * kS * kS;
#pragma unroll
    for (int mt = 0; mt < 4; mt++) {
        int row = i0 + (wm << 6) + (mt << 4) + (lane >> 2);
#pragma unroll
        for (int nt = 0; nt < 4; nt++) {
            int col = j0 + (wn << 5) + (nt << 3) + ((lane & 3) << 1);
            *(float2*)(Cb + (size_t)row * kS + col) =
                make_float2(acc[mt][nt][0] * 0.125f, acc[mt][nt][1] * 0.125f);
            *(float2*)(Cb + (size_t)(row + 8) * kS + col) =
                make_float2(acc[mt][nt][2] * 0.125f, acc[mt][nt][3] * 0.125f);
        }
    }
}

// ============================================================
// AV: O = P @ V per (b,h).  M=512, N=64, K=512. 128x64 tile, 4 warps.
// ============================================================
__global__ __launch_bounds__(128, 2) void av_tc(
    const float* __restrict__ P, const float* __restrict__ v,
    float* __restrict__ o)
{
    __shared__ uint32_t As[128][36];  // P tile [i][j]
    __shared__ uint32_t Bs[32][72];   // V tile [j][d]
    const int bh = blockIdx.y;
    const int b = bh >> 3, h = bh & 7;
    const int i0 = blockIdx.x << 7;
    const float* Pb = P + (size_t)bh * kS * kS;
    const float* Vb = v + (size_t)b * kS * kD + h * kDPH;
    const int tid = threadIdx.x;
    const int lane = tid & 31, warp = tid >> 5;
    const int wm = warp >> 1, wn = warp & 1;

    float4 pa[8], pb[4];
#pragma unroll
    for (int it = 0; it < 8; it++) {
        int idx = tid + (it << 7);
        int row = idx >> 3, kq = (idx & 7) << 2;
        pa[it] = *(const float4*)(Pb + (size_t)(i0 + row) * kS + kq);
    }
#pragma unroll
    for (int it = 0; it < 4; it++) {
        int idx = tid + (it << 7);
        int kr = idx >> 4, nq = (idx & 15) << 2;
        pb[it] = *(const float4*)(Vb + (size_t)kr * kD + nq);
    }
    float acc[4][4][4] = {};
    for (int ch = 0; ch < kS / 32; ch++) {
#pragma unroll
        for (int it = 0; it < 8; it++) {
            int idx = tid + (it << 7);
            int row = idx >> 3, kq = (idx & 7) << 2;
            As[row][kq + 0] = f2tf(pa[it].x); As[row][kq + 1] = f2tf(pa[it].y);
            As[row][kq + 2] = f2tf(pa[it].z); As[row][kq + 3] = f2tf(pa[it].w);
        }
#pragma unroll
        for (int it = 0; it < 4; it++) {
            int idx = tid + (it << 7);
            int kr = idx >> 4, nq = (idx & 15) << 2;
            Bs[kr][nq + 0] = f2tf(pb[it].x); Bs[kr][nq + 1] = f2tf(pb[it].y);
            Bs[kr][nq + 2] = f2tf(pb[it].z); Bs[kr][nq + 3] = f2tf(pb[it].w);
        }
        __syncthreads();
        if (ch + 1 < kS / 32) {
            int j0 = (ch + 1) << 5;
#pragma unroll
            for (int it = 0; it < 8; it++) {
                int idx = tid + (it << 7);
                int row = idx >> 3, kq = (idx & 7) << 2;
                pa[it] = *(const float4*)(Pb + (size_t)(i0 + row) * kS + j0 + kq);
            }
#pragma unroll
            for (int it = 0; it < 4; it++) {
                int idx = tid + (it << 7);
                int kr = idx >> 4, nq = (idx & 15) << 2;
                pb[it] = *(const float4*)(Vb + (size_t)(j0 + kr) * kD + nq);
            }
        }
#pragma unroll
        for (int kk = 0; kk < 32; kk += 8) {
            uint32_t af[4][4], bf[4][2];
#pragma unroll
            for (int mt = 0; mt < 4; mt++) {
                int r = (wm << 6) + (mt << 4) + (lane >> 2);
                int kc = kk + (lane & 3);
                af[mt][0] = As[r][kc];
                af[mt][1] = As[r + 8][kc];
                af[mt][2] = As[r][kc + 4];
                af[mt][3] = As[r + 8][kc + 4];
            }
#pragma unroll
            for (int nt = 0; nt < 4; nt++) {
                int n = (wn << 5) + (nt << 3) + (lane >> 2);
                int kc = kk + (lane & 3);
                bf[nt][0] = Bs[kc][n];
                bf[nt][1] = Bs[kc + 4][n];
            }
#pragma unroll
            for (int mt = 0; mt < 4; mt++)
#pragma unroll
                for (int nt = 0; nt < 4; nt++)
                    mma8(acc[mt][nt], af[mt], bf[nt]);
        }
        __syncthreads();
    }
#pragma unroll
    for (int mt = 0; mt < 4; mt++) {
        int row = i0 + (wm << 6) + (mt << 4) + (lane >> 2);
#pragma unroll
        for (int nt = 0; nt < 4; nt++) {
            int col = (wn << 5) + (nt << 3) + ((lane & 3) << 1);
            *(float2*)(o + (size_t)(b * kS + row) * kD + h * kDPH + col) =
                make_float2(acc[mt][nt][0], acc[mt][nt][1]);
            *(float2*)(o + (size_t)(b * kS + row + 8) * kD + h * kDPH + col) =
                make_float2(acc[mt][nt][2], acc[mt][nt][3]);
        }
    }
}

// ---------------- relation bias scatters into scores ----------------
__global__ __launch_bounds__(256) void relbias_pc_kernel(
    const int* __restrict__ pci, const float* __restrict__ rel,
    float* __restrict__ scores)
{
    int idx = blockIdx.x * blockDim.x + threadIdx.x;
    if (idx >= kNPC * kH) return;
    int e = idx >> 3, h = idx & 7;
    int b = pci[e * 3 + 0], i = pci[e * 3 + 1], j = pci[e * 3 + 2];
    size_t base = (size_t)(b * kH + h) * kS;
    atomicAdd(&scores[(base + i) * kS + j], rel[0]);
    atomicAdd(&scores[(base + j) * kS + i], rel[1]);
}

__global__ __launch_bounds__(256) void relbias_sib_kernel(
    const int* __restrict__ sbi, const float* __restrict__ rel,
    float* __restrict__ scores)
{
    int idx = blockIdx.x * blockDim.x + threadIdx.x;
    if (idx >= kNS * kH) return;
    int e = idx >> 3, h = idx & 7;
    int b = sbi[e * 3 + 0], i = sbi[e * 3 + 1], j = sbi[e * 3 + 2];
    size_t base = (size_t)(b * kH + h) * kS;
    float r2 = rel[2];
    atomicAdd(&scores[(base + i) * kS + j], r2);
    atomicAdd(&scores[(base + j) * kS + i], r2);
}

// ---------------- softmax over last dim (row length 512), warp per row ----------------
__global__ __launch_bounds__(256) void softmax_kernel(float* __restrict__ sc)
{
    const size_t row = (size_t)blockIdx.x * 8 + (threadIdx.x >> 5);
    const int lane = threadIdx.x & 31;
    float* p = sc + row * kS;
    float v[16];
    float mx = -1e30f;
#pragma unroll
    for (int t = 0; t < 16; t++) { v[t] = p[lane + t * 32]; mx = fmaxf(mx, v[t]); }
#pragma unroll
    for (int s = 16; s; s >>= 1) mx = fmaxf(mx, __shfl_xor_sync(0xffffffffu, mx, s));
    float sum = 0.0f;
#pragma unroll
    for (int t = 0; t < 16; t++) { v[t] = expf(v[t] - mx); sum += v[t]; }
#pragma unroll
    for (int s = 16; s; s >>= 1) sum += __shfl_xor_sync(0xffffffffu, sum, s);
    float inv = 1.0f / sum;
#pragma unroll
    for (int t = 0; t < 16; t++) p[lane + t * 32] = v[t] * inv;
}

// ---------------- LN(a + r), warp per row ----------------
__global__ __launch_bounds__(256) void ln_residual_kernel(
    const float* __restrict__ a, const float* __restrict__ r,
    const float* __restrict__ g, const float* __restrict__ bet,
    float* __restrict__ out)
{
    const size_t row = (size_t)blockIdx.x * 8 + (threadIdx.x >> 5);
    const int lane = threadIdx.x & 31;
    const float* ap = a + row * kD;
    const float* rp = r + row * kD;
    float v[16];
    float sum = 0.0f;
#pragma unroll
    for (int t = 0; t < 16; t++) {
        v[t] = ap[lane + t * 32] + rp[lane + t * 32];
        sum += v[t];
    }
#pragma unroll
    for (int s = 16; s; s >>= 1) sum += __shfl_xor_sync(0xffffffffu, sum, s);
    float mean = sum * (1.0f / kD);
    float s2 = 0.0f;
#pragma unroll
    for (int t = 0; t < 16; t++) { float d = v[t] - mean; s2 += d * d; }
#pragma unroll
    for (int s = 16; s; s >>= 1) s2 += __shfl_xor_sync(0xffffffffu, s2, s);
    float rstd = rsqrtf(s2 * (1.0f / kD) + 1e-5f);
#pragma unroll
    for (int t = 0; t < 16; t++) {
        int c = lane + t * 32;
        out[row * kD + c] = (v[t] - mean) * rstd * g[c] + bet[c];
    }
}

// ---------------- final logits ----------------
__global__ __launch_bounds__(256) void logits_kernel(
    const float* __restrict__ x, const float* __restrict__ w,
    float* __restrict__ out)
{
    int gw = (blockIdx.x * blockDim.x + threadIdx.x) >> 5;
    int lane = threadIdx.x & 31;
    if (gw >= kB * kVOCAB) return;
    int b = gw >> 10;
    int vcb = gw & (kVOCAB - 1);
    const float* xr = x + ((size_t)b * kS + (kS - 1)) * kD;
    const float* wr = w + (size_t)vcb * kD;
    float s = 0.0f;
#pragma unroll
    for (int t = 0; t < 16; t++) s += xr[lane + t * 32] * wr[lane + t * 32];
#pragma unroll
    for (int sh = 16; sh; sh >>= 1) s += __shfl_xor_sync(0xffffffffu, s, sh);
    if (lane == 0) out[gw] = s;
}

// ---------------- host launcher ----------------
extern "C" void kernel_launch(void* const* d_in, const int* in_sizes, int n_in,
                              void* d_out, int out_size)
{
    (void)in_sizes; (void)n_in; (void)out_size;
    const int*   raw_x = (const int*)d_in[0];
    const int*   deg   = (const int*)d_in[1];
    const int*   pci   = (const int*)d_in[2];
    const int*   pcn   = (const int*)d_in[3];
    const int*   sbi   = (const int*)d_in[4];
    const int*   sbn   = (const int*)d_in[5];
    const float* vemb  = (const float*)d_in[6];
    const float* demb  = (const float*)d_in[7];
    const float* are   = (const float*)d_in[8];
    const float* rel   = (const float*)d_in[9];
    const float* Wq    = (const float*)d_in[10];
    const float* bq    = (const float*)d_in[11];
    const float* Wk    = (const float*)d_in[12];
    const float* bk    = (const float*)d_in[13];
    const float* Wv    = (const float*)d_in[14];
    const float* bv    = (const float*)d_in[15];
    const float* Wo    = (const float*)d_in[16];
    const float* bo    = (const float*)d_in[17];
    const float* W1    = (const float*)d_in[18];
    const float* b1    = (const float*)d_in[19];
    const float* W2    = (const float*)d_in[20];
    const float* b2    = (const float*)d_in[21];
    const float* lng   = (const float*)d_in[22];
    const float* lnb   = (const float*)d_in[23];
    const float* logw  = (const float*)d_in[24];
    float* out = (float*)d_out;

    float *x, *q, *k, *v, *o, *t, *ff, *sc;
    cudaGetSymbolAddress((void**)&x,  g_x);
    cudaGetSymbolAddress((void**)&q,  g_q);
    cudaGetSymbolAddress((void**)&k,  g_k);
    cudaGetSymbolAddress((void**)&v,  g_v);
    cudaGetSymbolAddress((void**)&o,  g_o);
    cudaGetSymbolAddress((void**)&t,  g_t);
    cudaGetSymbolAddress((void**)&ff, g_ff);
    cudaGetSymbolAddress((void**)&sc, g_scores);

    embed_kernel<<<kM, 128>>>(raw_x, deg, vemb, demb, x);
    relnow_kernel<<<(kB * kD + 255) / 256, 256>>>(pcn, sbn, are, x);

    const dim3 gD(kD / 128, kM / 128);       // N=512 GEMMs: (4, 64)
    const dim3 gFF(kDFF / 128, kM / 128);    // N=2048 GEMM: (16, 64)
    const dim3 gSc(kS / 128, kS / 128, kB * kH);
    const dim3 gAv(kS / 128, kB * kH);

    for (int l = 0; l < kL; l++) {
        const float* wq = Wq + (size_t)l * kD * kD;
        const float* wk = Wk + (size_t)l * kD * kD;
        const float* wv = Wv + (size_t)l * kD * kD;
        const float* wo = Wo + (size_t)l * kD * kD;
        const float* w1 = W1 + (size_t)l * kDFF * kD;
        const float* w2 = W2 + (size_t)l * kD * kDFF;
        const float* bql = bq + (size_t)l * kD;
        const float* bkl = bk + (size_t)l * kD;
        const float* bvl = bv + (size_t)l * kD;
        const float* bol = bo + (size_t)l * kD;
        const float* b1l = b1 + (size_t)l * kDFF;
        const float* b2l = b2 + (size_t)l * kD;
        const float* lngl = lng + (size_t)l * kD;
        const float* lnbl = lnb + (size_t)l * kD;

        gemm_tc<false><<<gD, 256>>>(x, wq, bql, q, kM, kD, kD);
        gemm_tc<false><<<gD, 256>>>(x, wk, bkl, k, kM, kD, kD);
        gemm_tc<false><<<gD, 256>>>(x, wv, bvl, v, kM, kD, kD);

        scores_tc<<<gSc, 256>>>(q, k, sc);
        relbias_pc_kernel<<<(kNPC * kH + 255) / 256, 256>>>(pci, rel, sc);
        relbias_sib_kernel<<<(kNS * kH + 255) / 256, 256>>>(sbi, rel, sc);
        softmax_kernel<<<(kB * kH * kS) / 8, 256>>>(sc);
        av_tc<<<gAv, 128>>>(sc, v, o);

        gemm_tc<false><<<gD, 256>>>(o, wo, bol, t, kM, kD, kD);
        ln_residual_kernel<<<kM / 8, 256>>>(x, t, lngl, lnbl, x);

        gemm_tc<true><<<gFF, 256>>>(x, w1, b1l, ff, kM, kDFF, kD);
        gemm_tc<false><<<gD, 256>>>(ff, w2, b2l, t, kM, kD, kDFF);
        ln_residual_kernel<<<kM / 8, 256>>>(x, t, lngl, lnbl, x);
    }

    logits_kernel<<<(kB * kVOCAB * 32 + 255) / 256, 256>>>(x, logw, out);
}

// round 3
// speedup vs baseline: 3.7004x; 1.1851x over previous
#include <cuda_runtime.h>
#include <math.h>
#include <stdint.h>

// ---------------- problem constants ----------------
constexpr int kB = 16;
constexpr int kS = 512;
constexpr int kD = 512;
constexpr int kH = 8;
constexpr int kL = 6;
constexpr int kDFF = 2048;
constexpr int kVOCAB = 1024;
constexpr int kNPC = 4096;
constexpr int kNS = 4096;
constexpr int kM = kB * kS;  // 8192 rows
constexpr int kQKVN = 3 * kD; // 1536

// ---------------- scratch (static device globals; no allocations) ----------------
__device__ float g_x[(size_t)kM * kD];      // residual stream (full precision)
__device__ float g_xr[(size_t)kM * kD];     // rounded copy for GEMM input
__device__ float g_qkv[(size_t)kM * kQKVN]; // fused QKV output (rounded)
__device__ float g_att[(size_t)kM * kD];    // attention output (rounded)
__device__ float g_t[(size_t)kM * kD];      // pre-LN branch
__device__ float g_ff[(size_t)kM * kDFF];   // FFN hidden (rounded)
__device__ float g_bias[(size_t)kB * kS * kS];   // dense relation bias
__device__ float g_wqkv[(size_t)kL * kQKVN * kD];
__device__ float g_bqkv[(size_t)kL * kQKVN];
__device__ float g_wo[(size_t)kL * kD * kD];
__device__ float g_w1[(size_t)kL * kDFF * kD];
__device__ float g_w2[(size_t)kL * kD * kDFF];

// ---------------- tf32 helpers ----------------
__device__ __forceinline__ uint32_t f2tf(float f) {
    uint32_t u;
    asm("cvt.rna.tf32.f32 %0, %1;" : "=r"(u) : "f"(f));
    return u;
}
__device__ __forceinline__ float tfr(float f) { return __uint_as_float(f2tf(f)); }

__device__ __forceinline__ void mma8(float* c, const uint32_t* a, const uint32_t* b) {
    asm volatile(
        "mma.sync.aligned.m16n8k8.row.col.f32.tf32.tf32.f32 "
        "{%0,%1,%2,%3},{%4,%5,%6,%7},{%8,%9},{%0,%1,%2,%3};"
        : "+f"(c[0]), "+f"(c[1]), "+f"(c[2]), "+f"(c[3])
        : "r"(a[0]), "r"(a[1]), "r"(a[2]), "r"(a[3]), "r"(b[0]), "r"(b[1]));
}

__device__ __forceinline__ void cpa16(float* smem_dst, const float* gsrc) {
    uint32_t sa = (uint32_t)__cvta_generic_to_shared(smem_dst);
    asm volatile("cp.async.cg.shared.global [%0], [%1], 16;" :: "r"(sa), "l"(gsrc) : "memory");
}
__device__ __forceinline__ void cpa_commit() {
    asm volatile("cp.async.commit_group;" ::: "memory");
}
__device__ __forceinline__ void cpa_wait0() {
    asm volatile("cp.async.wait_group 0;" ::: "memory");
}
__device__ __forceinline__ void cpa_wait1() {
    asm volatile("cp.async.wait_group 1;" ::: "memory");
}

// ---------------- prep: weights → rounded scratch ----------------
__global__ __launch_bounds__(256) void prep_qkv_w(
    const float* __restrict__ Wq, const float* __restrict__ Wk,
    const float* __restrict__ Wv, float* __restrict__ wout)
{
    size_t n = (size_t)kL * kQKVN * kD;
    for (size_t idx = (size_t)blockIdx.x * blockDim.x + threadIdx.x; idx < n;
         idx += (size_t)gridDim.x * blockDim.x) {
        size_t l = idx / ((size_t)kQKVN * kD);
        size_t rem = idx % ((size_t)kQKVN * kD);
        int r = (int)(rem / kD), c = (int)(rem % kD);
        float v;
        if (r < kD)            v = Wq[(l * kD + r) * kD + c];
        else if (r < 2 * kD)   v = Wk[(l * kD + (r - kD)) * kD + c];
        else                   v = Wv[(l * kD + (r - 2 * kD)) * kD + c];
        wout[idx] = tfr(v);
    }
}

__global__ __launch_bounds__(256) void prep_qkv_b(
    const float* __restrict__ bq, const float* __restrict__ bk,
    const float* __restrict__ bv, float* __restrict__ bout)
{
    int idx = blockIdx.x * blockDim.x + threadIdx.x;
    if (idx >= kL * kQKVN) return;
    int l = idx / kQKVN, r = idx % kQKVN;
    float v;
    if (r < kD)          v = bq[l * kD + r];
    else if (r < 2 * kD) v = bk[l * kD + (r - kD)];
    else                 v = bv[l * kD + (r - 2 * kD)];
    bout[idx] = v;
}

__global__ __launch_bounds__(256) void round_copy(
    const float* __restrict__ src, float* __restrict__ dst, size_t n)
{
    for (size_t i = (size_t)blockIdx.x * blockDim.x + threadIdx.x; i < n;
         i += (size_t)gridDim.x * blockDim.x)
        dst[i] = tfr(src[i]);
}

// ---------------- dense relation-bias matrix ----------------
__global__ __launch_bounds__(256) void zero_bias(float* __restrict__ bias)
{
    size_t n = (size_t)kB * kS * kS;
    for (size_t i = (size_t)blockIdx.x * blockDim.x + threadIdx.x; i < n;
         i += (size_t)gridDim.x * blockDim.x)
        bias[i] = 0.0f;
}

__global__ __launch_bounds__(256) void scatter_pc(
    const int* __restrict__ pci, const float* __restrict__ rel, float* __restrict__ bias)
{
    int e = blockIdx.x * blockDim.x + threadIdx.x;
    if (e >= kNPC) return;
    int b = pci[e * 3 + 0], i = pci[e * 3 + 1], j = pci[e * 3 + 2];
    atomicAdd(&bias[((size_t)b * kS + i) * kS + j], rel[0]);
    atomicAdd(&bias[((size_t)b * kS + j) * kS + i], rel[1]);
}

__global__ __launch_bounds__(256) void scatter_sib(
    const int* __restrict__ sbi, const float* __restrict__ rel, float* __restrict__ bias)
{
    int e = blockIdx.x * blockDim.x + threadIdx.x;
    if (e >= kNS) return;
    int b = sbi[e * 3 + 0], i = sbi[e * 3 + 1], j = sbi[e * 3 + 2];
    float r2 = rel[2];
    atomicAdd(&bias[((size_t)b * kS + i) * kS + j], r2);
    atomicAdd(&bias[((size_t)b * kS + j) * kS + i], r2);
}

// ---------------- embedding + positional + degree ----------------
__global__ __launch_bounds__(128) void embed_kernel(
    const int* __restrict__ raw_x, const int* __restrict__ deg,
    const float* __restrict__ vemb, const float* __restrict__ demb,
    float* __restrict__ x)
{
    const int row = blockIdx.x;
    const int s = row & (kS - 1);
    const int tok = raw_x[row];
    const int dg = deg[row];
    const float c0 = -logf(10000.0f) / (float)kD;
    for (int c = threadIdx.x; c < kD; c += blockDim.x) {
        int p = c >> 1;
        float ang = (float)s * expf((float)(2 * p) * c0);
        float pe = (c & 1) ? cosf(ang) : sinf(ang);
        x[(size_t)row * kD + c] = vemb[(size_t)tok * kD + c] + pe + demb[(size_t)dg * kD + c];
    }
}

__global__ __launch_bounds__(256) void relnow_kernel(
    const int* __restrict__ pcn, const int* __restrict__ sn,
    const float* __restrict__ are, float* __restrict__ x)
{
    int idx = blockIdx.x * blockDim.x + threadIdx.x;
    if (idx >= kB * kD) return;
    int b = idx / kD, c = idx % kD;
    {
        int bb = pcn[b * 2 + 0], ss = pcn[b * 2 + 1];
        atomicAdd(&x[((size_t)bb * kS + ss) * kD + c], are[c]);
    }
    {
        int bb = sn[b * 2 + 0], ss = sn[b * 2 + 1];
        atomicAdd(&x[((size_t)bb * kS + ss) * kD + c], are[kD + c]);
    }
}

// ============================================================
// Tensor-core GEMM w/ cp.async double buffer.
// C[M,N] = A[M,K] @ W[N,K]^T + bias, optional relu, optional tf32-round.
// Inputs A,W MUST be pre-rounded to tf32 values.
// 128x128 tile, 8 warps (64x32), BK=32, 2 stages, 2 CTAs/SM.
// ============================================================
constexpr int kStageFl = 128 * 36;  // floats per stage per operand

template <bool RELU, bool ROUND>
__global__ __launch_bounds__(256, 2) void gemm_tc(
    const float* __restrict__ A, const float* __restrict__ W,
    const float* __restrict__ bias, float* __restrict__ C,
    int M, int N, int K)
{
    extern __shared__ float sm[];
    float* As = sm;                    // [2][128][36]
    float* Bs = sm + 2 * kStageFl;     // [2][128][36]
    const int tid = threadIdx.x;
    const int lane = tid & 31, warp = tid >> 5;
    const int wm = warp >> 2, wn = warp & 3;
    const int m0 = blockIdx.y << 7, n0 = blockIdx.x << 7;

    const int lrow = tid >> 3;            // 0..31 per iter chunk of rows
    const int lkq = (tid & 7) << 2;       // k offset (float4)

    auto issue = [&](int ch, int st) {
        const float* Ab = A + (size_t)m0 * K + (size_t)ch * 32 + lkq;
        const float* Wb = W + (size_t)n0 * K + (size_t)ch * 32 + lkq;
        float* Ad = As + st * kStageFl + lkq;
        float* Bd = Bs + st * kStageFl + lkq;
#pragma unroll
        for (int it = 0; it < 4; it++) {
            int row = lrow + (it << 5);
            cpa16(Ad + row * 36, Ab + (size_t)row * K);
            cpa16(Bd + row * 36, Wb + (size_t)row * K);
        }
        cpa_commit();
    };

    float acc[4][4][4] = {};
    const int nch = K >> 5;
    issue(0, 0);
    for (int ch = 0; ch < nch; ch++) {
        const int st = ch & 1;
        if (ch + 1 < nch) { issue(ch + 1, st ^ 1); cpa_wait1(); }
        else              { cpa_wait0(); }
        __syncthreads();
        const float* Ar = As + st * kStageFl;
        const float* Br = Bs + st * kStageFl;
#pragma unroll
        for (int kk = 0; kk < 32; kk += 8) {
            uint32_t af[4][4], bf[4][2];
            int kc = kk + (lane & 3);
#pragma unroll
            for (int mt = 0; mt < 4; mt++) {
                int r = (wm << 6) + (mt << 4) + (lane >> 2);
                af[mt][0] = __float_as_uint(Ar[r * 36 + kc]);
                af[mt][1] = __float_as_uint(Ar[(r + 8) * 36 + kc]);
                af[mt][2] = __float_as_uint(Ar[r * 36 + kc + 4]);
                af[mt][3] = __float_as_uint(Ar[(r + 8) * 36 + kc + 4]);
            }
#pragma unroll
            for (int nt = 0; nt < 4; nt++) {
                int n = (wn << 5) + (nt << 3) + (lane >> 2);
                bf[nt][0] = __float_as_uint(Br[n * 36 + kc]);
                bf[nt][1] = __float_as_uint(Br[n * 36 + kc + 4]);
            }
#pragma unroll
            for (int mt = 0; mt < 4; mt++)
#pragma unroll
                for (int nt = 0; nt < 4; nt++)
                    mma8(acc[mt][nt], af[mt], bf[nt]);
        }
        __syncthreads();
    }
#pragma unroll
    for (int mt = 0; mt < 4; mt++) {
        int row = m0 + (wm << 6) + (mt << 4) + (lane >> 2);
#pragma unroll
        for (int nt = 0; nt < 4; nt++) {
            int col = n0 + (wn << 5) + (nt << 3) + ((lane & 3) << 1);
            float bb0 = bias[col], bb1 = bias[col + 1];
            float v0 = acc[mt][nt][0] + bb0, v1 = acc[mt][nt][1] + bb1;
            float v2 = acc[mt][nt][2] + bb0, v3 = acc[mt][nt][3] + bb1;
            if (RELU) {
                v0 = fmaxf(v0, 0.0f); v1 = fmaxf(v1, 0.0f);
                v2 = fmaxf(v2, 0.0f); v3 = fmaxf(v3, 0.0f);
            }
            if (ROUND) { v0 = tfr(v0); v1 = tfr(v1); v2 = tfr(v2); v3 = tfr(v3); }
            *(float2*)(C + (size_t)row * N + col) = make_float2(v0, v1);
            *(float2*)(C + (size_t)(row + 8) * N + col) = make_float2(v2, v3);
        }
    }
}

// ============================================================
// Fused flash attention with additive dense bias.
// grid (4 i-tiles, B*H). 256 thr, warp owns 16 rows. j-tile 64.
// qkv: [kM][1536], bias: [B][S][S], out: [kM][512] (rounded).
// ============================================================
constexpr int kQsOff = 0;               // [128][68]
constexpr int kPsOff = 128 * 68;        // [128][68]  (K tile lives in rows 0..63)
constexpr int kVsOff = 2 * 128 * 68;    // [64][68]
constexpr int kFlashSmemFl = 2 * 128 * 68 + 64 * 68;

__global__ __launch_bounds__(256, 2) void flash_attn(
    const float* __restrict__ qkv, const float* __restrict__ bias,
    float* __restrict__ out)
{
    extern __shared__ float sm[];
    float* Qs = sm + kQsOff;
    float* Ps = sm + kPsOff;
    float* Vs = sm + kVsOff;
    const int bh = blockIdx.y;
    const int b = bh >> 3, h = bh & 7;
    const int i0 = blockIdx.x << 7;
    const int tid = threadIdx.x;
    const int lane = tid & 31, w = tid >> 5;
    const int quad = lane & 3;
    const int r0l = (w << 4) + (lane >> 2);     // local row 0..127 (first half)
    const size_t rowbase = (size_t)b * kS;      // row offset into qkv/out/bias

    // load Q tile (128 x 64) via cp.async
    {
        const float* Qg = qkv + (rowbase + i0) * kQKVN + h * 64;
#pragma unroll
        for (int it = 0; it < 8; it++) {
            int idx = tid + (it << 8);
            int row = idx >> 4, q4 = (idx & 15) << 2;
            cpa16(Qs + row * 68 + q4, Qg + (size_t)row * kQKVN + q4);
        }
        cpa_commit();
    }

    float oacc[8][4] = {};
    float mh[2] = {-1e30f, -1e30f};
    float lh[2] = {0.0f, 0.0f};

    for (int jt = 0; jt < 8; jt++) {
        const int j0 = jt << 6;
        // load K (into Ps rows 0..63) and V
        {
            const float* Kg = qkv + (rowbase + j0) * kQKVN + kD + h * 64;
            const float* Vg = qkv + (rowbase + j0) * kQKVN + 2 * kD + h * 64;
#pragma unroll
            for (int it = 0; it < 4; it++) {
                int idx = tid + (it << 8);
                int jr = idx >> 4, q4 = (idx & 15) << 2;
                cpa16(Ps + jr * 68 + q4, Kg + (size_t)jr * kQKVN + q4);
                cpa16(Vs + jr * 68 + q4, Vg + (size_t)jr * kQKVN + q4);
            }
            cpa_commit();
        }
        cpa_wait0();
        __syncthreads();

        // S = Q @ K^T  (16 rows x 64 cols per warp)
        float s[8][4] = {};
#pragma unroll
        for (int kk = 0; kk < 8; kk++) {
            int kc = (kk << 3) + quad;
            uint32_t af[4];
            af[0] = __float_as_uint(Qs[r0l * 68 + kc]);
            af[1] = __float_as_uint(Qs[(r0l + 8) * 68 + kc]);
            af[2] = __float_as_uint(Qs[r0l * 68 + kc + 4]);
            af[3] = __float_as_uint(Qs[(r0l + 8) * 68 + kc + 4]);
#pragma unroll
            for (int nt = 0; nt < 8; nt++) {
                int n = (nt << 3) + (lane >> 2);
                uint32_t bf[2];
                bf[0] = __float_as_uint(Ps[n * 68 + kc]);
                bf[1] = __float_as_uint(Ps[n * 68 + kc + 4]);
                mma8(s[nt], af, bf);
            }
        }
        __syncthreads();   // all warps done reading K before P overwrites it

        // scale + bias
        const size_t bi1 = (rowbase + i0 + r0l) * kS + j0;
        const size_t bi2 = (rowbase + i0 + r0l + 8) * kS + j0;
#pragma unroll
        for (int nt = 0; nt < 8; nt++) {
            int jc = (nt << 3) + (quad << 1);
            float2 z1 = *(const float2*)(bias + bi1 + jc);
            float2 z2 = *(const float2*)(bias + bi2 + jc);
            s[nt][0] = s[nt][0] * 0.125f + z1.x;
            s[nt][1] = s[nt][1] * 0.125f + z1.y;
            s[nt][2] = s[nt][2] * 0.125f + z2.x;
            s[nt][3] = s[nt][3] * 0.125f + z2.y;
        }
        // row max
        float mx0 = -1e30f, mx1 = -1e30f;
#pragma unroll
        for (int nt = 0; nt < 8; nt++) {
            mx0 = fmaxf(mx0, fmaxf(s[nt][0], s[nt][1]));
            mx1 = fmaxf(mx1, fmaxf(s[nt][2], s[nt][3]));
        }
        mx0 = fmaxf(mx0, __shfl_xor_sync(0xffffffffu, mx0, 1));
        mx0 = fmaxf(mx0, __shfl_xor_sync(0xffffffffu, mx0, 2));
        mx1 = fmaxf(mx1, __shfl_xor_sync(0xffffffffu, mx1, 1));
        mx1 = fmaxf(mx1, __shfl_xor_sync(0xffffffffu, mx1, 2));
        float mn0 = fmaxf(mh[0], mx0), mn1 = fmaxf(mh[1], mx1);
        float sc0 = __expf(mh[0] - mn0), sc1 = __expf(mh[1] - mn1);
        mh[0] = mn0; mh[1] = mn1;
        // exp, round, store P, partial sums
        float ps0 = 0.0f, ps1 = 0.0f;
#pragma unroll
        for (int nt = 0; nt < 8; nt++) {
            float p0 = tfr(__expf(s[nt][0] - mn0));
            float p1 = tfr(__expf(s[nt][1] - mn0));
            float p2 = tfr(__expf(s[nt][2] - mn1));
            float p3 = tfr(__expf(s[nt][3] - mn1));
            ps0 += p0 + p1; ps1 += p2 + p3;
            int jc = (nt << 3) + (quad << 1);
            *(float2*)(Ps + r0l * 68 + jc) = make_float2(p0, p1);
            *(float2*)(Ps + (r0l + 8) * 68 + jc) = make_float2(p2, p3);
        }
        ps0 += __shfl_xor_sync(0xffffffffu, ps0, 1);
        ps0 += __shfl_xor_sync(0xffffffffu, ps0, 2);
        ps1 += __shfl_xor_sync(0xffffffffu, ps1, 1);
        ps1 += __shfl_xor_sync(0xffffffffu, ps1, 2);
        lh[0] = lh[0] * sc0 + ps0;
        lh[1] = lh[1] * sc1 + ps1;
#pragma unroll
        for (int dt = 0; dt < 8; dt++) {
            oacc[dt][0] *= sc0; oacc[dt][1] *= sc0;
            oacc[dt][2] *= sc1; oacc[dt][3] *= sc1;
        }
        __syncthreads();   // P visible to all warps

        // O += P @ V
#pragma unroll
        for (int kk = 0; kk < 8; kk++) {
            int jc = (kk << 3) + quad;
            uint32_t af[4];
            af[0] = __float_as_uint(Ps[r0l * 68 + jc]);
            af[1] = __float_as_uint(Ps[(r0l + 8) * 68 + jc]);
            af[2] = __float_as_uint(Ps[r0l * 68 + jc + 4]);
            af[3] = __float_as_uint(Ps[(r0l + 8) * 68 + jc + 4]);
#pragma unroll
            for (int dt = 0; dt < 8; dt++) {
                int d = (dt << 3) + (lane >> 2);
                uint32_t bf[2];
                bf[0] = __float_as_uint(Vs[jc * 68 + d]);
                bf[1] = __float_as_uint(Vs[(jc + 4) * 68 + d]);
                mma8(oacc[dt], af, bf);
            }
        }
        __syncthreads();   // done with Ps/Vs before next tile's cp.async
    }

    // epilogue
    float inv0 = 1.0f / lh[0], inv1 = 1.0f / lh[1];
    float* o1 = out + (rowbase + i0 + r0l) * kD + h * 64;
    float* o2 = out + (rowbase + i0 + r0l + 8) * kD + h * 64;
#pragma unroll
    for (int dt = 0; dt < 8; dt++) {
        int dc = (dt << 3) + (quad << 1);
        *(float2*)(o1 + dc) = make_float2(tfr(oacc[dt][0] * inv0), tfr(oacc[dt][1] * inv0));
        *(float2*)(o2 + dc) = make_float2(tfr(oacc[dt][2] * inv1), tfr(oacc[dt][3] * inv1));
    }
}

// ---------------- LN(a + r): writes full + rounded copies ----------------
__global__ __launch_bounds__(256) void ln_residual_dual(
    const float* __restrict__ a, const float* __restrict__ r,
    const float* __restrict__ g, const float* __restrict__ bet,
    float* __restrict__ outf, float* __restrict__ outr)
{
    const size_t row = (size_t)blockIdx.x * 8 + (threadIdx.x >> 5);
    const int lane = threadIdx.x & 31;
    const float* ap = a + row * kD;
    const float* rp = r + row * kD;
    float v[16];
    float sum = 0.0f;
#pragma unroll
    for (int t = 0; t < 16; t++) {
        v[t] = ap[lane + t * 32] + rp[lane + t * 32];
        sum += v[t];
    }
#pragma unroll
    for (int s = 16; s; s >>= 1) sum += __shfl_xor_sync(0xffffffffu, sum, s);
    float mean = sum * (1.0f / kD);
    float s2 = 0.0f;
#pragma unroll
    for (int t = 0; t < 16; t++) { float d = v[t] - mean; s2 += d * d; }
#pragma unroll
    for (int s = 16; s; s >>= 1) s2 += __shfl_xor_sync(0xffffffffu, s2, s);
    float rstd = rsqrtf(s2 * (1.0f / kD) + 1e-5f);
#pragma unroll
    for (int t = 0; t < 16; t++) {
        int c = lane + t * 32;
        float o = (v[t] - mean) * rstd * g[c] + bet[c];
        outf[row * kD + c] = o;
        outr[row * kD + c] = tfr(o);
    }
}

// ---------------- final logits ----------------
__global__ __launch_bounds__(256) void logits_kernel(
    const float* __restrict__ x, const float* __restrict__ w,
    float* __restrict__ out)
{
    int gw = (blockIdx.x * blockDim.x + threadIdx.x) >> 5;
    int lane = threadIdx.x & 31;
    if (gw >= kB * kVOCAB) return;
    int b = gw >> 10;
    int vcb = gw & (kVOCAB - 1);
    const float* xr = x + ((size_t)b * kS + (kS - 1)) * kD;
    const float* wr = w + (size_t)vcb * kD;
    float s = 0.0f;
#pragma unroll
    for (int t = 0; t < 16; t++) s += xr[lane + t * 32] * wr[lane + t * 32];
#pragma unroll
    for (int sh = 16; sh; sh >>= 1) s += __shfl_xor_sync(0xffffffffu, s, sh);
    if (lane == 0) out[gw] = s;
}

// ---------------- host launcher ----------------
extern "C" void kernel_launch(void* const* d_in, const int* in_sizes, int n_in,
                              void* d_out, int out_size)
{
    (void)in_sizes; (void)n_in; (void)out_size;
    const int*   raw_x = (const int*)d_in[0];
    const int*   deg   = (const int*)d_in[1];
    const int*   pci   = (const int*)d_in[2];
    const int*   pcn   = (const int*)d_in[3];
    const int*   sbi   = (const int*)d_in[4];
    const int*   sbn   = (const int*)d_in[5];
    const float* vemb  = (const float*)d_in[6];
    const float* demb  = (const float*)d_in[7];
    const float* are   = (const float*)d_in[8];
    const float* rel   = (const float*)d_in[9];
    const float* Wq    = (const float*)d_in[10];
    const float* bq    = (const float*)d_in[11];
    const float* Wk    = (const float*)d_in[12];
    const float* bk    = (const float*)d_in[13];
    const float* Wv    = (const float*)d_in[14];
    const float* bv    = (const float*)d_in[15];
    const float* Wo    = (const float*)d_in[16];
    const float* bo    = (const float*)d_in[17];
    const float* W1    = (const float*)d_in[18];
    const float* b1    = (const float*)d_in[19];
    const float* W2    = (const float*)d_in[20];
    const float* b2    = (const float*)d_in[21];
    const float* lng   = (const float*)d_in[22];
    const float* lnb   = (const float*)d_in[23];
    const float* logw  = (const float*)d_in[24];
    float* out = (float*)d_out;

    float *x, *xr, *qkv, *att, *t, *ff, *bias;
    float *wqkv, *bqkv, *wo, *w1, *w2;
    cudaGetSymbolAddress((void**)&x,    g_x);
    cudaGetSymbolAddress((void**)&xr,   g_xr);
    cudaGetSymbolAddress((void**)&qkv,  g_qkv);
    cudaGetSymbolAddress((void**)&att,  g_att);
    cudaGetSymbolAddress((void**)&t,    g_t);
    cudaGetSymbolAddress((void**)&ff,   g_ff);
    cudaGetSymbolAddress((void**)&bias, g_bias);
    cudaGetSymbolAddress((void**)&wqkv, g_wqkv);
    cudaGetSymbolAddress((void**)&bqkv, g_bqkv);
    cudaGetSymbolAddress((void**)&wo,   g_wo);
    cudaGetSymbolAddress((void**)&w1,   g_w1);
    cudaGetSymbolAddress((void**)&w2,   g_w2);

    const int gemmSmem = 4 * kStageFl * sizeof(float);       // 73,728
    const int flashSmem = kFlashSmemFl * sizeof(float);      // 87,040
    cudaFuncSetAttribute(gemm_tc<false, true>,  cudaFuncAttributeMaxDynamicSharedMemorySize, gemmSmem);
    cudaFuncSetAttribute(gemm_tc<false, false>, cudaFuncAttributeMaxDynamicSharedMemorySize, gemmSmem);
    cudaFuncSetAttribute(gemm_tc<true, true>,   cudaFuncAttributeMaxDynamicSharedMemorySize, gemmSmem);
    cudaFuncSetAttribute(flash_attn,            cudaFuncAttributeMaxDynamicSharedMemorySize, flashSmem);

    // ---- prep (cheap, once per replay) ----
    prep_qkv_w<<<2048, 256>>>(Wq, Wk, Wv, wqkv);
    prep_qkv_b<<<(kL * kQKVN + 255) / 256, 256>>>(bq, bk, bv, bqkv);
    round_copy<<<2048, 256>>>(Wo, wo, (size_t)kL * kD * kD);
    round_copy<<<2048, 256>>>(W1, w1, (size_t)kL * kDFF * kD);
    round_copy<<<2048, 256>>>(W2, w2, (size_t)kL * kD * kDFF);
    zero_bias<<<2048, 256>>>(bias);
    scatter_pc<<<(kNPC + 255) / 256, 256>>>(pci, rel, bias);
    scatter_sib<<<(kNS + 255) / 256, 256>>>(sbi, rel, bias);

    embed_kernel<<<kM, 128>>>(raw_x, deg, vemb, demb, x);
    relnow_kernel<<<(kB * kD + 255) / 256, 256>>>(pcn, sbn, are, x);
    round_copy<<<2048, 256>>>(x, xr, (size_t)kM * kD);

    const dim3 gQKV(kQKVN / 128, kM / 128);  // (12, 64)
    const dim3 gD(kD / 128, kM / 128);       // (4, 64)
    const dim3 gFF(kDFF / 128, kM / 128);    // (16, 64)
    const dim3 gFl(kS / 128, kB * kH);       // (4, 128)

    for (int l = 0; l < kL; l++) {
        const float* wqkvl = wqkv + (size_t)l * kQKVN * kD;
        const float* bqkvl = bqkv + (size_t)l * kQKVN;
        const float* wol = wo + (size_t)l * kD * kD;
        const float* w1l = w1 + (size_t)l * kDFF * kD;
        const float* w2l = w2 + (size_t)l * kD * kDFF;
        const float* bol = bo + (size_t)l * kD;
        const float* b1l = b1 + (size_t)l * kDFF;
        const float* b2l = b2 + (size_t)l * kD;
        const float* lngl = lng + (size_t)l * kD;
        const float* lnbl = lnb + (size_t)l * kD;

        gemm_tc<false, true><<<gQKV, 256, gemmSmem>>>(xr, wqkvl, bqkvl, qkv, kM, kQKVN, kD);
        flash_attn<<<gFl, 256, flashSmem>>>(qkv, bias, att);
        gemm_tc<false, false><<<gD, 256, gemmSmem>>>(att, wol, bol, t, kM, kD, kD);
        ln_residual_dual<<<kM / 8, 256>>>(x, t, lngl, lnbl, x, xr);

        gemm_tc<true, true><<<gFF, 256, gemmSmem>>>(xr, w1l, b1l, ff, kM, kDFF, kD);
        gemm_tc<false, false><<<gD, 256, gemmSmem>>>(ff, w2l, b2l, t, kM, kD, kDFF);
        ln_residual_dual<<<kM / 8, 256>>>(x, t, lngl, lnbl, x, xr);
    }

    logits_kernel<<<(kB * kVOCAB * 32 + 255) / 256, 256>>>(x, logw, out);
}

// round 4
// speedup vs baseline: 3.9963x; 1.0800x over previous
#include <cuda_runtime.h>
#include <math.h>
#include <stdint.h>

// ---------------- problem constants ----------------
constexpr int kB = 16;
constexpr int kS = 512;
constexpr int kD = 512;
constexpr int kH = 8;
constexpr int kL = 6;
constexpr int kDFF = 2048;
constexpr int kVOCAB = 1024;
constexpr int kNPC = 4096;
constexpr int kNS = 4096;
constexpr int kM = kB * kS;  // 8192 rows
constexpr int kQKVN = 3 * kD; // 1536

// ---------------- scratch (static device globals; no allocations) ----------------
__device__ float g_x[(size_t)kM * kD];      // residual stream (full precision)
__device__ float g_xr[(size_t)kM * kD];     // rounded copy for GEMM input
__device__ float g_qkv[(size_t)kM * kQKVN]; // fused QKV output (rounded)
__device__ float g_att[(size_t)kM * kD];    // attention output (rounded)
__device__ float g_t[(size_t)kM * kD];      // pre-LN branch
__device__ float g_ff[(size_t)kM * kDFF];   // FFN hidden (rounded)
__device__ float g_bias[(size_t)kB * kS * kS];   // dense relation bias
__device__ float g_wqkv[(size_t)kL * kQKVN * kD];
__device__ float g_bqkv[(size_t)kL * kQKVN];
__device__ float g_wo[(size_t)kL * kD * kD];
__device__ float g_w1[(size_t)kL * kDFF * kD];
__device__ float g_w2[(size_t)kL * kD * kDFF];

// ---------------- tf32 helpers ----------------
__device__ __forceinline__ uint32_t f2tf(float f) {
    uint32_t u;
    asm("cvt.rna.tf32.f32 %0, %1;" : "=r"(u) : "f"(f));
    return u;
}
__device__ __forceinline__ float tfr(float f) { return __uint_as_float(f2tf(f)); }

__device__ __forceinline__ void mma8(float* c, const uint32_t* a, const uint32_t* b) {
    asm volatile(
        "mma.sync.aligned.m16n8k8.row.col.f32.tf32.tf32.f32 "
        "{%0,%1,%2,%3},{%4,%5,%6,%7},{%8,%9},{%0,%1,%2,%3};"
        : "+f"(c[0]), "+f"(c[1]), "+f"(c[2]), "+f"(c[3])
        : "r"(a[0]), "r"(a[1]), "r"(a[2]), "r"(a[3]), "r"(b[0]), "r"(b[1]));
}

// ldmatrix x4: for tf32, one m8n8.b16 matrix == 8 rows x 4 floats; lane/reg
// mapping coincides with the tf32 mma fragment layout.
__device__ __forceinline__ void ldsm_x4(uint32_t* r, const float* p) {
    uint32_t addr = (uint32_t)__cvta_generic_to_shared(p);
    asm volatile("ldmatrix.sync.aligned.m8n8.x4.shared.b16 {%0,%1,%2,%3}, [%4];"
        : "=r"(r[0]), "=r"(r[1]), "=r"(r[2]), "=r"(r[3]) : "r"(addr));
}

__device__ __forceinline__ void cpa16(float* smem_dst, const float* gsrc) {
    uint32_t sa = (uint32_t)__cvta_generic_to_shared(smem_dst);
    asm volatile("cp.async.cg.shared.global [%0], [%1], 16;" :: "r"(sa), "l"(gsrc) : "memory");
}
__device__ __forceinline__ void cpa_commit() {
    asm volatile("cp.async.commit_group;" ::: "memory");
}
__device__ __forceinline__ void cpa_wait0() {
    asm volatile("cp.async.wait_group 0;" ::: "memory");
}
__device__ __forceinline__ void cpa_wait1() {
    asm volatile("cp.async.wait_group 1;" ::: "memory");
}

// ---------------- prep: weights → rounded scratch ----------------
__global__ __launch_bounds__(256) void prep_qkv_w(
    const float* __restrict__ Wq, const float* __restrict__ Wk,
    const float* __restrict__ Wv, float* __restrict__ wout)
{
    size_t n = (size_t)kL * kQKVN * kD;
    for (size_t idx = (size_t)blockIdx.x * blockDim.x + threadIdx.x; idx < n;
         idx += (size_t)gridDim.x * blockDim.x) {
        size_t l = idx / ((size_t)kQKVN * kD);
        size_t rem = idx % ((size_t)kQKVN * kD);
        int r = (int)(rem / kD), c = (int)(rem % kD);
        float v;
        if (r < kD)            v = Wq[(l * kD + r) * kD + c];
        else if (r < 2 * kD)   v = Wk[(l * kD + (r - kD)) * kD + c];
        else                   v = Wv[(l * kD + (r - 2 * kD)) * kD + c];
        wout[idx] = tfr(v);
    }
}

__global__ __launch_bounds__(256) void prep_qkv_b(
    const float* __restrict__ bq, const float* __restrict__ bk,
    const float* __restrict__ bv, float* __restrict__ bout)
{
    int idx = blockIdx.x * blockDim.x + threadIdx.x;
    if (idx >= kL * kQKVN) return;
    int l = idx / kQKVN, r = idx % kQKVN;
    float v;
    if (r < kD)          v = bq[l * kD + r];
    else if (r < 2 * kD) v = bk[l * kD + (r - kD)];
    else                 v = bv[l * kD + (r - 2 * kD)];
    bout[idx] = v;
}

__global__ __launch_bounds__(256) void round_copy(
    const float* __restrict__ src, float* __restrict__ dst, size_t n)
{
    for (size_t i = (size_t)blockIdx.x * blockDim.x + threadIdx.x; i < n;
         i += (size_t)gridDim.x * blockDim.x)
        dst[i] = tfr(src[i]);
}

// ---------------- dense relation-bias matrix ----------------
__global__ __launch_bounds__(256) void zero_bias(float* __restrict__ bias)
{
    size_t n = (size_t)kB * kS * kS;
    for (size_t i = (size_t)blockIdx.x * blockDim.x + threadIdx.x; i < n;
         i += (size_t)gridDim.x * blockDim.x)
        bias[i] = 0.0f;
}

__global__ __launch_bounds__(256) void scatter_pc(
    const int* __restrict__ pci, const float* __restrict__ rel, float* __restrict__ bias)
{
    int e = blockIdx.x * blockDim.x + threadIdx.x;
    if (e >= kNPC) return;
    int b = pci[e * 3 + 0], i = pci[e * 3 + 1], j = pci[e * 3 + 2];
    atomicAdd(&bias[((size_t)b * kS + i) * kS + j], rel[0]);
    atomicAdd(&bias[((size_t)b * kS + j) * kS + i], rel[1]);
}

__global__ __launch_bounds__(256) void scatter_sib(
    const int* __restrict__ sbi, const float* __restrict__ rel, float* __restrict__ bias)
{
    int e = blockIdx.x * blockDim.x + threadIdx.x;
    if (e >= kNS) return;
    int b = sbi[e * 3 + 0], i = sbi[e * 3 + 1], j = sbi[e * 3 + 2];
    float r2 = rel[2];
    atomicAdd(&bias[((size_t)b * kS + i) * kS + j], r2);
    atomicAdd(&bias[((size_t)b * kS + j) * kS + i], r2);
}

// ---------------- embedding + positional + degree ----------------
__global__ __launch_bounds__(128) void embed_kernel(
    const int* __restrict__ raw_x, const int* __restrict__ deg,
    const float* __restrict__ vemb, const float* __restrict__ demb,
    float* __restrict__ x)
{
    const int row = blockIdx.x;
    const int s = row & (kS - 1);
    const int tok = raw_x[row];
    const int dg = deg[row];
    const float c0 = -logf(10000.0f) / (float)kD;
    for (int c = threadIdx.x; c < kD; c += blockDim.x) {
        int p = c >> 1;
        float ang = (float)s * expf((float)(2 * p) * c0);
        float pe = (c & 1) ? cosf(ang) : sinf(ang);
        x[(size_t)row * kD + c] = vemb[(size_t)tok * kD + c] + pe + demb[(size_t)dg * kD + c];
    }
}

__global__ __launch_bounds__(256) void relnow_kernel(
    const int* __restrict__ pcn, const int* __restrict__ sn,
    const float* __restrict__ are, float* __restrict__ x)
{
    int idx = blockIdx.x * blockDim.x + threadIdx.x;
    if (idx >= kB * kD) return;
    int b = idx / kD, c = idx % kD;
    {
        int bb = pcn[b * 2 + 0], ss = pcn[b * 2 + 1];
        atomicAdd(&x[((size_t)bb * kS + ss) * kD + c], are[c]);
    }
    {
        int bb = sn[b * 2 + 0], ss = sn[b * 2 + 1];
        atomicAdd(&x[((size_t)bb * kS + ss) * kD + c], are[kD + c]);
    }
}

// ============================================================
// Tensor-core GEMM w/ cp.async double buffer + ldmatrix fragments.
// C[M,N] = A[M,K] @ W[N,K]^T + bias, optional relu, optional tf32-round.
// Inputs A,W MUST be pre-rounded to tf32 values.
// 128x128 tile, 8 warps (64x32), BK=32, 2 stages, 2 CTAs/SM.
// ============================================================
constexpr int kStageFl = 128 * 36;  // floats per stage per operand

template <bool RELU, bool ROUND>
__global__ __launch_bounds__(256, 2) void gemm_tc(
    const float* __restrict__ A, const float* __restrict__ W,
    const float* __restrict__ bias, float* __restrict__ C,
    int M, int N, int K)
{
    extern __shared__ float sm[];
    float* As = sm;                    // [2][128][36]
    float* Bs = sm + 2 * kStageFl;     // [2][128][36]
    const int tid = threadIdx.x;
    const int lane = tid & 31, warp = tid >> 5;
    const int wm = warp >> 2, wn = warp & 3;
    const int m0 = blockIdx.y << 7, n0 = blockIdx.x << 7;

    const int lrow = tid >> 3;            // 0..31 per iter chunk of rows
    const int lkq = (tid & 7) << 2;       // k offset (float4)

    // ldmatrix per-lane address components
    const int lg = lane >> 3, llr = lane & 7;
    const int a_radd = (lg & 1) << 3;     // +8 rows for matrices 1,3
    const int a_kadd = (lg >> 1) << 2;    // +4 k for matrices 2,3
    const int b_nadd = (lg >> 1) << 3;    // +8 n for matrices 2,3
    const int b_kadd = (lg & 1) << 2;     // +4 k for matrices 1,3

    auto issue = [&](int ch, int st) {
        const float* Ab = A + (size_t)m0 * K + (size_t)ch * 32 + lkq;
        const float* Wb = W + (size_t)n0 * K + (size_t)ch * 32 + lkq;
        float* Ad = As + st * kStageFl + lkq;
        float* Bd = Bs + st * kStageFl + lkq;
#pragma unroll
        for (int it = 0; it < 4; it++) {
            int row = lrow + (it << 5);
            cpa16(Ad + row * 36, Ab + (size_t)row * K);
            cpa16(Bd + row * 36, Wb + (size_t)row * K);
        }
        cpa_commit();
    };

    float acc[4][4][4] = {};
    const int nch = K >> 5;
    issue(0, 0);
    for (int ch = 0; ch < nch; ch++) {
        const int st = ch & 1;
        if (ch + 1 < nch) { issue(ch + 1, st ^ 1); cpa_wait1(); }
        else              { cpa_wait0(); }
        __syncthreads();
        const float* Ar = As + st * kStageFl;
        const float* Br = Bs + st * kStageFl;
#pragma unroll
        for (int kk = 0; kk < 32; kk += 8) {
            uint32_t af[4][4], bp[2][4];
#pragma unroll
            for (int mt = 0; mt < 4; mt++)
                ldsm_x4(af[mt], Ar + ((wm << 6) + (mt << 4) + a_radd + llr) * 36 + kk + a_kadd);
#pragma unroll
            for (int p = 0; p < 2; p++)
                ldsm_x4(bp[p], Br + ((wn << 5) + (p << 4) + b_nadd + llr) * 36 + kk + b_kadd);
#pragma unroll
            for (int mt = 0; mt < 4; mt++)
#pragma unroll
                for (int nt = 0; nt < 4; nt++)
                    mma8(acc[mt][nt], af[mt], &bp[nt >> 1][(nt & 1) << 1]);
        }
        __syncthreads();
    }
#pragma unroll
    for (int mt = 0; mt < 4; mt++) {
        int row = m0 + (wm << 6) + (mt << 4) + (lane >> 2);
#pragma unroll
        for (int nt = 0; nt < 4; nt++) {
            int col = n0 + (wn << 5) + (nt << 3) + ((lane & 3) << 1);
            float bb0 = bias[col], bb1 = bias[col + 1];
            float v0 = acc[mt][nt][0] + bb0, v1 = acc[mt][nt][1] + bb1;
            float v2 = acc[mt][nt][2] + bb0, v3 = acc[mt][nt][3] + bb1;
            if (RELU) {
                v0 = fmaxf(v0, 0.0f); v1 = fmaxf(v1, 0.0f);
                v2 = fmaxf(v2, 0.0f); v3 = fmaxf(v3, 0.0f);
            }
            if (ROUND) { v0 = tfr(v0); v1 = tfr(v1); v2 = tfr(v2); v3 = tfr(v3); }
            *(float2*)(C + (size_t)row * N + col) = make_float2(v0, v1);
            *(float2*)(C + (size_t)(row + 8) * N + col) = make_float2(v2, v3);
        }
    }
}

// ============================================================
// Fused flash attention with additive dense bias.
// grid (4 i-tiles, B*H). 256 thr, warp owns 16 rows. j-tile 64.
// qkv: [kM][1536], bias: [B][S][S], out: [kM][512] (rounded).
// ============================================================
constexpr int kQsOff = 0;               // [128][68]
constexpr int kPsOff = 128 * 68;        // [128][68]  (K tile lives in rows 0..63)
constexpr int kVsOff = 2 * 128 * 68;    // [64][68]
constexpr int kFlashSmemFl = 2 * 128 * 68 + 64 * 68;

__global__ __launch_bounds__(256, 2) void flash_attn(
    const float* __restrict__ qkv, const float* __restrict__ bias,
    float* __restrict__ out)
{
    extern __shared__ float sm[];
    float* Qs = sm + kQsOff;
    float* Ps = sm + kPsOff;
    float* Vs = sm + kVsOff;
    const int bh = blockIdx.y;
    const int b = bh >> 3, h = bh & 7;
    const int i0 = blockIdx.x << 7;
    const int tid = threadIdx.x;
    const int lane = tid & 31, w = tid >> 5;
    const int quad = lane & 3;
    const int r0l = (w << 4) + (lane >> 2);     // local row 0..127 (first half)
    const size_t rowbase = (size_t)b * kS;      // row offset into qkv/out/bias

    // ldmatrix lane components
    const int lg = lane >> 3, llr = lane & 7;
    const int a_radd = (lg & 1) << 3;
    const int a_kadd = (lg >> 1) << 2;
    const int b_nadd = (lg >> 1) << 3;
    const int b_kadd = (lg & 1) << 2;

    // load Q tile (128 x 64) via cp.async
    {
        const float* Qg = qkv + (rowbase + i0) * kQKVN + h * 64;
#pragma unroll
        for (int it = 0; it < 8; it++) {
            int idx = tid + (it << 8);
            int row = idx >> 4, q4 = (idx & 15) << 2;
            cpa16(Qs + row * 68 + q4, Qg + (size_t)row * kQKVN + q4);
        }
        cpa_commit();
    }

    float oacc[8][4] = {};
    float mh[2] = {-1e30f, -1e30f};
    float lh[2] = {0.0f, 0.0f};

    for (int jt = 0; jt < 8; jt++) {
        const int j0 = jt << 6;
        // load K (into Ps rows 0..63) and V
        {
            const float* Kg = qkv + (rowbase + j0) * kQKVN + kD + h * 64;
            const float* Vg = qkv + (rowbase + j0) * kQKVN + 2 * kD + h * 64;
#pragma unroll
            for (int it = 0; it < 4; it++) {
                int idx = tid + (it << 8);
                int jr = idx >> 4, q4 = (idx & 15) << 2;
                cpa16(Ps + jr * 68 + q4, Kg + (size_t)jr * kQKVN + q4);
                cpa16(Vs + jr * 68 + q4, Vg + (size_t)jr * kQKVN + q4);
            }
            cpa_commit();
        }
        cpa_wait0();
        __syncthreads();

        // S = Q @ K^T  (16 rows x 64 cols per warp)
        float s[8][4] = {};
#pragma unroll
        for (int kk = 0; kk < 8; kk++) {
            int kc = kk << 3;
            uint32_t af[4], bp[4][4];
            ldsm_x4(af, Qs + ((w << 4) + a_radd + llr) * 68 + kc + a_kadd);
#pragma unroll
            for (int p = 0; p < 4; p++)
                ldsm_x4(bp[p], Ps + ((p << 4) + b_nadd + llr) * 68 + kc + b_kadd);
#pragma unroll
            for (int nt = 0; nt < 8; nt++)
                mma8(s[nt], af, &bp[nt >> 1][(nt & 1) << 1]);
        }
        __syncthreads();   // all warps done reading K before P overwrites it

        // scale + bias
        const size_t bi1 = (rowbase + i0 + r0l) * kS + j0;
        const size_t bi2 = (rowbase + i0 + r0l + 8) * kS + j0;
#pragma unroll
        for (int nt = 0; nt < 8; nt++) {
            int jc = (nt << 3) + (quad << 1);
            float2 z1 = *(const float2*)(bias + bi1 + jc);
            float2 z2 = *(const float2*)(bias + bi2 + jc);
            s[nt][0] = s[nt][0] * 0.125f + z1.x;
            s[nt][1] = s[nt][1] * 0.125f + z1.y;
            s[nt][2] = s[nt][2] * 0.125f + z2.x;
            s[nt][3] = s[nt][3] * 0.125f + z2.y;
        }
        // row max
        float mx0 = -1e30f, mx1 = -1e30f;
#pragma unroll
        for (int nt = 0; nt < 8; nt++) {
            mx0 = fmaxf(mx0, fmaxf(s[nt][0], s[nt][1]));
            mx1 = fmaxf(mx1, fmaxf(s[nt][2], s[nt][3]));
        }
        mx0 = fmaxf(mx0, __shfl_xor_sync(0xffffffffu, mx0, 1));
        mx0 = fmaxf(mx0, __shfl_xor_sync(0xffffffffu, mx0, 2));
        mx1 = fmaxf(mx1, __shfl_xor_sync(0xffffffffu, mx1, 1));
        mx1 = fmaxf(mx1, __shfl_xor_sync(0xffffffffu, mx1, 2));
        float mn0 = fmaxf(mh[0], mx0), mn1 = fmaxf(mh[1], mx1);
        float sc0 = __expf(mh[0] - mn0), sc1 = __expf(mh[1] - mn1);
        mh[0] = mn0; mh[1] = mn1;
        // exp, round, store P, partial sums
        float ps0 = 0.0f, ps1 = 0.0f;
#pragma unroll
        for (int nt = 0; nt < 8; nt++) {
            float p0 = tfr(__expf(s[nt][0] - mn0));
            float p1 = tfr(__expf(s[nt][1] - mn0));
            float p2 = tfr(__expf(s[nt][2] - mn1));
            float p3 = tfr(__expf(s[nt][3] - mn1));
            ps0 += p0 + p1; ps1 += p2 + p3;
            int jc = (nt << 3) + (quad << 1);
            *(float2*)(Ps + r0l * 68 + jc) = make_float2(p0, p1);
            *(float2*)(Ps + (r0l + 8) * 68 + jc) = make_float2(p2, p3);
        }
        ps0 += __shfl_xor_sync(0xffffffffu, ps0, 1);
        ps0 += __shfl_xor_sync(0xffffffffu, ps0, 2);
        ps1 += __shfl_xor_sync(0xffffffffu, ps1, 1);
        ps1 += __shfl_xor_sync(0xffffffffu, ps1, 2);
        lh[0] = lh[0] * sc0 + ps0;
        lh[1] = lh[1] * sc1 + ps1;
#pragma unroll
        for (int dt = 0; dt < 8; dt++) {
            oacc[dt][0] *= sc0; oacc[dt][1] *= sc0;
            oacc[dt][2] *= sc1; oacc[dt][3] *= sc1;
        }
        __syncthreads();   // P visible to all warps

        // O += P @ V  (P via ldmatrix; V scalar — transposed access)
#pragma unroll
        for (int kk = 0; kk < 8; kk++) {
            int jc0 = kk << 3;
            int jc = jc0 + quad;
            uint32_t af[4];
            ldsm_x4(af, Ps + ((w << 4) + a_radd + llr) * 68 + jc0 + a_kadd);
#pragma unroll
            for (int dt = 0; dt < 8; dt++) {
                int d = (dt << 3) + (lane >> 2);
                uint32_t bf[2];
                bf[0] = __float_as_uint(Vs[jc * 68 + d]);
                bf[1] = __float_as_uint(Vs[(jc + 4) * 68 + d]);
                mma8(oacc[dt], af, bf);
            }
        }
        __syncthreads();   // done with Ps/Vs before next tile's cp.async
    }

    // epilogue
    float inv0 = 1.0f / lh[0], inv1 = 1.0f / lh[1];
    float* o1 = out + (rowbase + i0 + r0l) * kD + h * 64;
    float* o2 = out + (rowbase + i0 + r0l + 8) * kD + h * 64;
#pragma unroll
    for (int dt = 0; dt < 8; dt++) {
        int dc = (dt << 3) + (quad << 1);
        *(float2*)(o1 + dc) = make_float2(tfr(oacc[dt][0] * inv0), tfr(oacc[dt][1] * inv0));
        *(float2*)(o2 + dc) = make_float2(tfr(oacc[dt][2] * inv1), tfr(oacc[dt][3] * inv1));
    }
}

// ---------------- LN(a + r): writes full + rounded copies ----------------
__global__ __launch_bounds__(256) void ln_residual_dual(
    const float* __restrict__ a, const float* __restrict__ r,
    const float* __restrict__ g, const float* __restrict__ bet,
    float* __restrict__ outf, float* __restrict__ outr)
{
    const size_t row = (size_t)blockIdx.x * 8 + (threadIdx.x >> 5);
    const int lane = threadIdx.x & 31;
    const float* ap = a + row * kD;
    const float* rp = r + row * kD;
    float v[16];
    float sum = 0.0f;
#pragma unroll
    for (int t = 0; t < 16; t++) {
        v[t] = ap[lane + t * 32] + rp[lane + t * 32];
        sum += v[t];
    }
#pragma unroll
    for (int s = 16; s; s >>= 1) sum += __shfl_xor_sync(0xffffffffu, sum, s);
    float mean = sum * (1.0f / kD);
    float s2 = 0.0f;
#pragma unroll
    for (int t = 0; t < 16; t++) { float d = v[t] - mean; s2 += d * d; }
#pragma unroll
    for (int s = 16; s; s >>= 1) s2 += __shfl_xor_sync(0xffffffffu, s2, s);
    float rstd = rsqrtf(s2 * (1.0f / kD) + 1e-5f);
#pragma unroll
    for (int t = 0; t < 16; t++) {
        int c = lane + t * 32;
        float o = (v[t] - mean) * rstd * g[c] + bet[c];
        outf[row * kD + c] = o;
        outr[row * kD + c] = tfr(o);
    }
}

// ---------------- final logits ----------------
__global__ __launch_bounds__(256) void logits_kernel(
    const float* __restrict__ x, const float* __restrict__ w,
    float* __restrict__ out)
{
    int gw = (blockIdx.x * blockDim.x + threadIdx.x) >> 5;
    int lane = threadIdx.x & 31;
    if (gw >= kB * kVOCAB) return;
    int b = gw >> 10;
    int vcb = gw & (kVOCAB - 1);
    const float* xr = x + ((size_t)b * kS + (kS - 1)) * kD;
    const float* wr = w + (size_t)vcb * kD;
    float s = 0.0f;
#pragma unroll
    for (int t = 0; t < 16; t++) s += xr[lane + t * 32] * wr[lane + t * 32];
#pragma unroll
    for (int sh = 16; sh; sh >>= 1) s += __shfl_xor_sync(0xffffffffu, s, sh);
    if (lane == 0) out[gw] = s;
}

// ---------------- host launcher ----------------
extern "C" void kernel_launch(void* const* d_in, const int* in_sizes, int n_in,
                              void* d_out, int out_size)
{
    (void)in_sizes; (void)n_in; (void)out_size;
    const int*   raw_x = (const int*)d_in[0];
    const int*   deg   = (const int*)d_in[1];
    const int*   pci   = (const int*)d_in[2];
    const int*   pcn   = (const int*)d_in[3];
    const int*   sbi   = (const int*)d_in[4];
    const int*   sbn   = (const int*)d_in[5];
    const float* vemb  = (const float*)d_in[6];
    const float* demb  = (const float*)d_in[7];
    const float* are   = (const float*)d_in[8];
    const float* rel   = (const float*)d_in[9];
    const float* Wq    = (const float*)d_in[10];
    const float* bq    = (const float*)d_in[11];
    const float* Wk    = (const float*)d_in[12];
    const float* bk    = (const float*)d_in[13];
    const float* Wv    = (const float*)d_in[14];
    const float* bv    = (const float*)d_in[15];
    const float* Wo    = (const float*)d_in[16];
    const float* bo    = (const float*)d_in[17];
    const float* W1    = (const float*)d_in[18];
    const float* b1    = (const float*)d_in[19];
    const float* W2    = (const float*)d_in[20];
    const float* b2    = (const float*)d_in[21];
    const float* lng   = (const float*)d_in[22];
    const float* lnb   = (const float*)d_in[23];
    const float* logw  = (const float*)d_in[24];
    float* out = (float*)d_out;

    float *x, *xr, *qkv, *att, *t, *ff, *bias;
    float *wqkv, *bqkv, *wo, *w1, *w2;
    cudaGetSymbolAddress((void**)&x,    g_x);
    cudaGetSymbolAddress((void**)&xr,   g_xr);
    cudaGetSymbolAddress((void**)&qkv,  g_qkv);
    cudaGetSymbolAddress((void**)&att,  g_att);
    cudaGetSymbolAddress((void**)&t,    g_t);
    cudaGetSymbolAddress((void**)&ff,   g_ff);
    cudaGetSymbolAddress((void**)&bias, g_bias);
    cudaGetSymbolAddress((void**)&wqkv, g_wqkv);
    cudaGetSymbolAddress((void**)&bqkv, g_bqkv);
    cudaGetSymbolAddress((void**)&wo,   g_wo);
    cudaGetSymbolAddress((void**)&w1,   g_w1);
    cudaGetSymbolAddress((void**)&w2,   g_w2);

    const int gemmSmem = 4 * kStageFl * sizeof(float);       // 73,728
    const int flashSmem = kFlashSmemFl * sizeof(float);      // 87,040
    cudaFuncSetAttribute(gemm_tc<false, true>,  cudaFuncAttributeMaxDynamicSharedMemorySize, gemmSmem);
    cudaFuncSetAttribute(gemm_tc<false, false>, cudaFuncAttributeMaxDynamicSharedMemorySize, gemmSmem);
    cudaFuncSetAttribute(gemm_tc<true, true>,   cudaFuncAttributeMaxDynamicSharedMemorySize, gemmSmem);
    cudaFuncSetAttribute(flash_attn,            cudaFuncAttributeMaxDynamicSharedMemorySize, flashSmem);

    // ---- prep (cheap, once per replay) ----
    prep_qkv_w<<<2048, 256>>>(Wq, Wk, Wv, wqkv);
    prep_qkv_b<<<(kL * kQKVN + 255) / 256, 256>>>(bq, bk, bv, bqkv);
    round_copy<<<2048, 256>>>(Wo, wo, (size_t)kL * kD * kD);
    round_copy<<<2048, 256>>>(W1, w1, (size_t)kL * kDFF * kD);
    round_copy<<<2048, 256>>>(W2, w2, (size_t)kL * kD * kDFF);
    zero_bias<<<2048, 256>>>(bias);
    scatter_pc<<<(kNPC + 255) / 256, 256>>>(pci, rel, bias);
    scatter_sib<<<(kNS + 255) / 256, 256>>>(sbi, rel, bias);

    embed_kernel<<<kM, 128>>>(raw_x, deg, vemb, demb, x);
    relnow_kernel<<<(kB * kD + 255) / 256, 256>>>(pcn, sbn, are, x);
    round_copy<<<2048, 256>>>(x, xr, (size_t)kM * kD);

    const dim3 gQKV(kQKVN / 128, kM / 128);  // (12, 64)
    const dim3 gD(kD / 128, kM / 128);       // (4, 64)
    const dim3 gFF(kDFF / 128, kM / 128);    // (16, 64)
    const dim3 gFl(kS / 128, kB * kH);       // (4, 128)

    for (int l = 0; l < kL; l++) {
        const float* wqkvl = wqkv + (size_t)l * kQKVN * kD;
        const float* bqkvl = bqkv + (size_t)l * kQKVN;
        const float* wol = wo + (size_t)l * kD * kD;
        const float* w1l = w1 + (size_t)l * kDFF * kD;
        const float* w2l = w2 + (size_t)l * kD * kDFF;
        const float* bol = bo + (size_t)l * kD;
        const float* b1l = b1 + (size_t)l * kDFF;
        const float* b2l = b2 + (size_t)l * kD;
        const float* lngl = lng + (size_t)l * kD;
        const float* lnbl = lnb + (size_t)l * kD;

        gemm_tc<false, true><<<gQKV, 256, gemmSmem>>>(xr, wqkvl, bqkvl, qkv, kM, kQKVN, kD);
        flash_attn<<<gFl, 256, flashSmem>>>(qkv, bias, att);
        gemm_tc<false, false><<<gD, 256, gemmSmem>>>(att, wol, bol, t, kM, kD, kD);
        ln_residual_dual<<<kM / 8, 256>>>(x, t, lngl, lnbl, x, xr);

        gemm_tc<true, true><<<gFF, 256, gemmSmem>>>(xr, w1l, b1l, ff, kM, kDFF, kD);
        gemm_tc<false, false><<<gD, 256, gemmSmem>>>(ff, w2l, b2l, t, kM, kD, kDFF);
        ln_residual_dual<<<kM / 8, 256>>>(x, t, lngl, lnbl, x, xr);
    }

    logits_kernel<<<(kB * kVOCAB * 32 + 255) / 256, 256>>>(x, logw, out);
}

// round 6
// speedup vs baseline: 4.2092x; 1.0533x over previous
#include <cuda_runtime.h>
#include <math.h>
#include <stdint.h>

// ---------------- problem constants ----------------
constexpr int kB = 16;
constexpr int kS = 512;
constexpr int kD = 512;
constexpr int kH = 8;
constexpr int kL = 6;
constexpr int kDFF = 2048;
constexpr int kVOCAB = 1024;
constexpr int kNPC = 4096;
constexpr int kNS = 4096;
constexpr int kM = kB * kS;  // 8192 rows
constexpr int kQKVN = 3 * kD; // 1536

// ---------------- scratch (static device globals; no allocations) ----------------
__device__ float g_x[(size_t)kM * kD];      // residual stream (full precision)
__device__ float g_xr[(size_t)kM * kD];     // rounded copy for GEMM input
__device__ float g_qkv[(size_t)kM * kQKVN]; // fused QKV output (V part unused)
__device__ float g_vt[(size_t)kM * kD];     // V transposed: [b][h*64+d][s]
__device__ float g_att[(size_t)kM * kD];    // attention output (rounded)
__device__ float g_t[(size_t)kM * kD];      // pre-LN branch
__device__ float g_ff[(size_t)kM * kDFF];   // FFN hidden (rounded)
__device__ float g_bias[(size_t)kB * kS * kS];   // dense relation bias
__device__ float g_wqkv[(size_t)kL * kQKVN * kD];
__device__ float g_bqkv[(size_t)kL * kQKVN];
__device__ float g_wo[(size_t)kL * kD * kD];
__device__ float g_w1[(size_t)kL * kDFF * kD];
__device__ float g_w2[(size_t)kL * kD * kDFF];

// ---------------- tf32 helpers ----------------
__device__ __forceinline__ uint32_t f2tf(float f) {
    uint32_t u;
    asm("cvt.rna.tf32.f32 %0, %1;" : "=r"(u) : "f"(f));
    return u;
}
__device__ __forceinline__ float tfr(float f) { return __uint_as_float(f2tf(f)); }

__device__ __forceinline__ void mma8(float* c, const uint32_t* a, const uint32_t* b) {
    asm volatile(
        "mma.sync.aligned.m16n8k8.row.col.f32.tf32.tf32.f32 "
        "{%0,%1,%2,%3},{%4,%5,%6,%7},{%8,%9},{%0,%1,%2,%3};"
        : "+f"(c[0]), "+f"(c[1]), "+f"(c[2]), "+f"(c[3])
        : "r"(a[0]), "r"(a[1]), "r"(a[2]), "r"(a[3]), "r"(b[0]), "r"(b[1]));
}

__device__ __forceinline__ void ldsm_x4(uint32_t* r, const float* p) {
    uint32_t addr = (uint32_t)__cvta_generic_to_shared(p);
    asm volatile("ldmatrix.sync.aligned.m8n8.x4.shared.b16 {%0,%1,%2,%3}, [%4];"
        : "=r"(r[0]), "=r"(r[1]), "=r"(r[2]), "=r"(r[3]) : "r"(addr));
}

__device__ __forceinline__ void cpa16(void* smem_dst, const void* gsrc) {
    uint32_t sa = (uint32_t)__cvta_generic_to_shared(smem_dst);
    asm volatile("cp.async.cg.shared.global [%0], [%1], 16;" :: "r"(sa), "l"(gsrc) : "memory");
}
__device__ __forceinline__ void cpa_commit() {
    asm volatile("cp.async.commit_group;" ::: "memory");
}
__device__ __forceinline__ void cpa_wait0() {
    asm volatile("cp.async.wait_group 0;" ::: "memory");
}
__device__ __forceinline__ void cpa_wait1() {
    asm volatile("cp.async.wait_group 1;" ::: "memory");
}

// ---------------- prep: weights → rounded scratch ----------------
__global__ __launch_bounds__(256) void prep_qkv_w(
    const float* __restrict__ Wq, const float* __restrict__ Wk,
    const float* __restrict__ Wv, float* __restrict__ wout)
{
    size_t n = (size_t)kL * kQKVN * kD;
    for (size_t idx = (size_t)blockIdx.x * blockDim.x + threadIdx.x; idx < n;
         idx += (size_t)gridDim.x * blockDim.x) {
        size_t l = idx / ((size_t)kQKVN * kD);
        size_t rem = idx % ((size_t)kQKVN * kD);
        int r = (int)(rem / kD), c = (int)(rem % kD);
        float v;
        if (r < kD)            v = Wq[(l * kD + r) * kD + c];
        else if (r < 2 * kD)   v = Wk[(l * kD + (r - kD)) * kD + c];
        else                   v = Wv[(l * kD + (r - 2 * kD)) * kD + c];
        wout[idx] = tfr(v);
    }
}

__global__ __launch_bounds__(256) void prep_qkv_b(
    const float* __restrict__ bq, const float* __restrict__ bk,
    const float* __restrict__ bv, float* __restrict__ bout)
{
    int idx = blockIdx.x * blockDim.x + threadIdx.x;
    if (idx >= kL * kQKVN) return;
    int l = idx / kQKVN, r = idx % kQKVN;
    float v;
    if (r < kD)          v = bq[l * kD + r];
    else if (r < 2 * kD) v = bk[l * kD + (r - kD)];
    else                 v = bv[l * kD + (r - 2 * kD)];
    bout[idx] = v;
}

__global__ __launch_bounds__(256) void round_copy(
    const float* __restrict__ src, float* __restrict__ dst, size_t n)
{
    for (size_t i = (size_t)blockIdx.x * blockDim.x + threadIdx.x; i < n;
         i += (size_t)gridDim.x * blockDim.x)
        dst[i] = tfr(src[i]);
}

// ---------------- dense relation-bias matrix ----------------
__global__ __launch_bounds__(256) void zero_bias(float* __restrict__ bias)
{
    size_t n = (size_t)kB * kS * kS;
    for (size_t i = (size_t)blockIdx.x * blockDim.x + threadIdx.x; i < n;
         i += (size_t)gridDim.x * blockDim.x)
        bias[i] = 0.0f;
}

__global__ __launch_bounds__(256) void scatter_pc(
    const int* __restrict__ pci, const float* __restrict__ rel, float* __restrict__ bias)
{
    int e = blockIdx.x * blockDim.x + threadIdx.x;
    if (e >= kNPC) return;
    int b = pci[e * 3 + 0], i = pci[e * 3 + 1], j = pci[e * 3 + 2];
    atomicAdd(&bias[((size_t)b * kS + i) * kS + j], rel[0]);
    atomicAdd(&bias[((size_t)b * kS + j) * kS + i], rel[1]);
}

__global__ __launch_bounds__(256) void scatter_sib(
    const int* __restrict__ sbi, const float* __restrict__ rel, float* __restrict__ bias)
{
    int e = blockIdx.x * blockDim.x + threadIdx.x;
    if (e >= kNS) return;
    int b = sbi[e * 3 + 0], i = sbi[e * 3 + 1], j = sbi[e * 3 + 2];
    float r2 = rel[2];
    atomicAdd(&bias[((size_t)b * kS + i) * kS + j], r2);
    atomicAdd(&bias[((size_t)b * kS + j) * kS + i], r2);
}

// ---------------- embedding + positional + degree ----------------
__global__ __launch_bounds__(128) void embed_kernel(
    const int* __restrict__ raw_x, const int* __restrict__ deg,
    const float* __restrict__ vemb, const float* __restrict__ demb,
    float* __restrict__ x)
{
    const int row = blockIdx.x;
    const int s = row & (kS - 1);
    const int tok = raw_x[row];
    const int dg = deg[row];
    const float c0 = -logf(10000.0f) / (float)kD;
    for (int c = threadIdx.x; c < kD; c += blockDim.x) {
        int p = c >> 1;
        float ang = (float)s * expf((float)(2 * p) * c0);
        float pe = (c & 1) ? cosf(ang) : sinf(ang);
        x[(size_t)row * kD + c] = vemb[(size_t)tok * kD + c] + pe + demb[(size_t)dg * kD + c];
    }
}

__global__ __launch_bounds__(256) void relnow_kernel(
    const int* __restrict__ pcn, const int* __restrict__ sn,
    const float* __restrict__ are, float* __restrict__ x)
{
    int idx = blockIdx.x * blockDim.x + threadIdx.x;
    if (idx >= kB * kD) return;
    int b = idx / kD, c = idx % kD;
    {
        int bb = pcn[b * 2 + 0], ss = pcn[b * 2 + 1];
        atomicAdd(&x[((size_t)bb * kS + ss) * kD + c], are[c]);
    }
    {
        int bb = sn[b * 2 + 0], ss = sn[b * 2 + 1];
        atomicAdd(&x[((size_t)bb * kS + ss) * kD + c], are[kD + c]);
    }
}

// ============================================================
// Tensor-core GEMM: 3-stage cp.async pipeline, one sync per chunk.
// C[M,N] = A[M,K] @ W[N,K]^T + bias, optional relu/round.
// MODE 0: normal output. MODE 1 (QKV): tiles with n0>=1024 (V) are
// written transposed into vt[b][hd][s]; Q,K tiles go to C as usual.
// 128x128 tile, 8 warps (64x32), BK=32. smem = 3 * 36KB = 108KB.
// ============================================================
constexpr int kStageFl = 2 * 128 * 36;   // A+B floats per stage
constexpr int kGemmSmemBytes = 3 * kStageFl * 4;   // 110,592

template <bool RELU, bool ROUND, int MODE>
__global__ __launch_bounds__(256, 2) void gemm_tc(
    const float* __restrict__ A, const float* __restrict__ W,
    const float* __restrict__ bias, float* __restrict__ C,
    float* __restrict__ vt, int M, int N, int K)
{
    extern __shared__ float sm[];
    const int tid = threadIdx.x;
    const int lane = tid & 31, warp = tid >> 5;
    const int wm = warp >> 2, wn = warp & 3;
    const int m0 = blockIdx.y << 7, n0 = blockIdx.x << 7;

    const int lrow = tid >> 3;            // 0..31
    const int lkq = (tid & 7) << 2;       // k offset (float4)

    const int lg = lane >> 3, llr = lane & 7;
    const int a_radd = (lg & 1) << 3;
    const int a_kadd = (lg >> 1) << 2;
    const int b_nadd = (lg >> 1) << 3;
    const int b_kadd = (lg & 1) << 2;

    auto issue = [&](int ch, int st) {
        const float* Ab = A + (size_t)m0 * K + (size_t)ch * 32 + lkq;
        const float* Wb = W + (size_t)n0 * K + (size_t)ch * 32 + lkq;
        float* Ad = sm + st * kStageFl + lkq;
        float* Bd = sm + st * kStageFl + (kStageFl >> 1) + lkq;
#pragma unroll
        for (int it = 0; it < 4; it++) {
            int row = lrow + (it << 5);
            cpa16(Ad + row * 36, Ab + (size_t)row * K);
            cpa16(Bd + row * 36, Wb + (size_t)row * K);
        }
        cpa_commit();
    };

    float acc[4][4][4] = {};
    const int nch = K >> 5;
    issue(0, 0);
    issue(1, 1);
    int st = 0, st2 = 2;   // compute stage, issue stage
    for (int ch = 0; ch < nch; ch++) {
        if (ch + 1 < nch) cpa_wait1(); else cpa_wait0();
        __syncthreads();
        if (ch + 2 < nch) issue(ch + 2, st2);
        const float* Ar = sm + st * kStageFl;
        const float* Br = Ar + (kStageFl >> 1);
#pragma unroll
        for (int kk = 0; kk < 32; kk += 8) {
            uint32_t af[4][4], bp[2][4];
#pragma unroll
            for (int mt = 0; mt < 4; mt++)
                ldsm_x4(af[mt], Ar + ((wm << 6) + (mt << 4) + a_radd + llr) * 36 + kk + a_kadd);
#pragma unroll
            for (int p = 0; p < 2; p++)
                ldsm_x4(bp[p], Br + ((wn << 5) + (p << 4) + b_nadd + llr) * 36 + kk + b_kadd);
#pragma unroll
            for (int mt = 0; mt < 4; mt++)
#pragma unroll
                for (int nt = 0; nt < 4; nt++)
                    mma8(acc[mt][nt], af[mt], &bp[nt >> 1][(nt & 1) << 1]);
        }
        st = (st == 2) ? 0 : st + 1;
        st2 = (st2 == 2) ? 0 : st2 + 1;
    }

    if (MODE == 1 && n0 >= 1024) {
        // V tile: write transposed into vt[b][hd][s]
        const int bidx = m0 >> 9;
        float* vtb = vt + ((size_t)bidx << 9) * kS;
#pragma unroll
        for (int mt = 0; mt < 4; mt++) {
            int s = (m0 & 511) + (wm << 6) + (mt << 4) + (lane >> 2);
#pragma unroll
            for (int nt = 0; nt < 4; nt++) {
                int col = n0 + (wn << 5) + (nt << 3) + ((lane & 3) << 1);
                int hd = col - 1024;
                float bb0 = bias[col], bb1 = bias[col + 1];
                float v0 = acc[mt][nt][0] + bb0, v1 = acc[mt][nt][1] + bb1;
                float v2 = acc[mt][nt][2] + bb0, v3 = acc[mt][nt][3] + bb1;
                if (ROUND) { v0 = tfr(v0); v1 = tfr(v1); v2 = tfr(v2); v3 = tfr(v3); }
                vtb[(size_t)hd * kS + s] = v0;
                vtb[(size_t)(hd + 1) * kS + s] = v1;
                vtb[(size_t)hd * kS + s + 8] = v2;
                vtb[(size_t)(hd + 1) * kS + s + 8] = v3;
            }
        }
        return;
    }
#pragma unroll
    for (int mt = 0; mt < 4; mt++) {
        int row = m0 + (wm << 6) + (mt << 4) + (lane >> 2);
#pragma unroll
        for (int nt = 0; nt < 4; nt++) {
            int col = n0 + (wn << 5) + (nt << 3) + ((lane & 3) << 1);
            float bb0 = bias[col], bb1 = bias[col + 1];
            float v0 = acc[mt][nt][0] + bb0, v1 = acc[mt][nt][1] + bb1;
            float v2 = acc[mt][nt][2] + bb0, v3 = acc[mt][nt][3] + bb1;
            if (RELU) {
                v0 = fmaxf(v0, 0.0f); v1 = fmaxf(v1, 0.0f);
                v2 = fmaxf(v2, 0.0f); v3 = fmaxf(v3, 0.0f);
            }
            if (ROUND) { v0 = tfr(v0); v1 = tfr(v1); v2 = tfr(v2); v3 = tfr(v3); }
            *(float2*)(C + (size_t)row * N + col) = make_float2(v0, v1);
            *(float2*)(C + (size_t)(row + 8) * N + col) = make_float2(v2, v3);
        }
    }
}

// ============================================================
// Fused flash attention with additive dense bias.
// Q,K from qkv [kM][1536]; V from vt [b][h*64+d][s] (transposed).
// P@V B-fragments via ldmatrix (no conflicted scalar LDS).
// ============================================================
constexpr int kQsOff = 0;               // [128][68]
constexpr int kPsOff = 128 * 68;        // [128][68]  (K tile lives in rows 0..63)
constexpr int kVsOff = 2 * 128 * 68;    // [64][68]   V^T tile: rows d, cols j
constexpr int kFlashSmemFl = 2 * 128 * 68 + 64 * 68;

__global__ __launch_bounds__(256, 2) void flash_attn(
    const float* __restrict__ qkv, const float* __restrict__ vt,
    const float* __restrict__ bias, float* __restrict__ out)
{
    extern __shared__ float sm[];
    float* Qs = sm + kQsOff;
    float* Ps = sm + kPsOff;
    float* Vs = sm + kVsOff;
    const int bh = blockIdx.y;
    const int b = bh >> 3, h = bh & 7;
    const int i0 = blockIdx.x << 7;
    const int tid = threadIdx.x;
    const int lane = tid & 31, w = tid >> 5;
    const int quad = lane & 3;
    const int r0l = (w << 4) + (lane >> 2);
    const size_t rowbase = (size_t)b * kS;

    const int lg = lane >> 3, llr = lane & 7;
    const int a_radd = (lg & 1) << 3;
    const int a_kadd = (lg >> 1) << 2;
    const int b_nadd = (lg >> 1) << 3;
    const int b_kadd = (lg & 1) << 2;

    {
        const float* Qg = qkv + (rowbase + i0) * kQKVN + h * 64;
#pragma unroll
        for (int it = 0; it < 8; it++) {
            int idx = tid + (it << 8);
            int row = idx >> 4, q4 = (idx & 15) << 2;
            cpa16(Qs + row * 68 + q4, Qg + (size_t)row * kQKVN + q4);
        }
        cpa_commit();
    }

    float oacc[8][4] = {};
    float mh[2] = {-1e30f, -1e30f};
    float lh[2] = {0.0f, 0.0f};

    const float* Vgb = vt + (rowbase << 3) * 64 + (size_t)h * 64 * kS;  // b*512*512 + h*64*512

    for (int jt = 0; jt < 8; jt++) {
        const int j0 = jt << 6;
        {
            const float* Kg = qkv + (rowbase + j0) * kQKVN + kD + h * 64;
#pragma unroll
            for (int it = 0; it < 4; it++) {
                int idx = tid + (it << 8);
                int jr = idx >> 4, q4 = (idx & 15) << 2;
                cpa16(Ps + jr * 68 + q4, Kg + (size_t)jr * kQKVN + q4);
            }
            // V^T tile: rows d 0..63, cols j 0..63 (coalesced from vt)
#pragma unroll
            for (int it = 0; it < 4; it++) {
                int idx = tid + (it << 8);
                int dr = idx >> 4, j4 = (idx & 15) << 2;
                cpa16(Vs + dr * 68 + j4, Vgb + (size_t)dr * kS + j0 + j4);
            }
            cpa_commit();
        }
        cpa_wait0();
        __syncthreads();

        float s[8][4] = {};
#pragma unroll
        for (int kk = 0; kk < 8; kk++) {
            int kc = kk << 3;
            uint32_t af[4], bp[4][4];
            ldsm_x4(af, Qs + ((w << 4) + a_radd + llr) * 68 + kc + a_kadd);
#pragma unroll
            for (int p = 0; p < 4; p++)
                ldsm_x4(bp[p], Ps + ((p << 4) + b_nadd + llr) * 68 + kc + b_kadd);
#pragma unroll
            for (int nt = 0; nt < 8; nt++)
                mma8(s[nt], af, &bp[nt >> 1][(nt & 1) << 1]);
        }
        __syncthreads();

        const size_t bi1 = (rowbase + i0 + r0l) * kS + j0;
        const size_t bi2 = (rowbase + i0 + r0l + 8) * kS + j0;
#pragma unroll
        for (int nt = 0; nt < 8; nt++) {
            int jc = (nt << 3) + (quad << 1);
            float2 z1 = *(const float2*)(bias + bi1 + jc);
            float2 z2 = *(const float2*)(bias + bi2 + jc);
            s[nt][0] = s[nt][0] * 0.125f + z1.x;
            s[nt][1] = s[nt][1] * 0.125f + z1.y;
            s[nt][2] = s[nt][2] * 0.125f + z2.x;
            s[nt][3] = s[nt][3] * 0.125f + z2.y;
        }
        float mx0 = -1e30f, mx1 = -1e30f;
#pragma unroll
        for (int nt = 0; nt < 8; nt++) {
            mx0 = fmaxf(mx0, fmaxf(s[nt][0], s[nt][1]));
            mx1 = fmaxf(mx1, fmaxf(s[nt][2], s[nt][3]));
        }
        mx0 = fmaxf(mx0, __shfl_xor_sync(0xffffffffu, mx0, 1));
        mx0 = fmaxf(mx0, __shfl_xor_sync(0xffffffffu, mx0, 2));
        mx1 = fmaxf(mx1, __shfl_xor_sync(0xffffffffu, mx1, 1));
        mx1 = fmaxf(mx1, __shfl_xor_sync(0xffffffffu, mx1, 2));
        float mn0 = fmaxf(mh[0], mx0), mn1 = fmaxf(mh[1], mx1);
        float sc0 = __expf(mh[0] - mn0), sc1 = __expf(mh[1] - mn1);
        mh[0] = mn0; mh[1] = mn1;
        float ps0 = 0.0f, ps1 = 0.0f;
#pragma unroll
        for (int nt = 0; nt < 8; nt++) {
            float p0 = tfr(__expf(s[nt][0] - mn0));
            float p1 = tfr(__expf(s[nt][1] - mn0));
            float p2 = tfr(__expf(s[nt][2] - mn1));
            float p3 = tfr(__expf(s[nt][3] - mn1));
            ps0 += p0 + p1; ps1 += p2 + p3;
            int jc = (nt << 3) + (quad << 1);
            *(float2*)(Ps + r0l * 68 + jc) = make_float2(p0, p1);
            *(float2*)(Ps + (r0l + 8) * 68 + jc) = make_float2(p2, p3);
        }
        ps0 += __shfl_xor_sync(0xffffffffu, ps0, 1);
        ps0 += __shfl_xor_sync(0xffffffffu, ps0, 2);
        ps1 += __shfl_xor_sync(0xffffffffu, ps1, 1);
        ps1 += __shfl_xor_sync(0xffffffffu, ps1, 2);
        lh[0] = lh[0] * sc0 + ps0;
        lh[1] = lh[1] * sc1 + ps1;
#pragma unroll
        for (int dt = 0; dt < 8; dt++) {
            oacc[dt][0] *= sc0; oacc[dt][1] *= sc0;
            oacc[dt][2] *= sc1; oacc[dt][3] *= sc1;
        }
        __syncthreads();

        // O += P @ V : A-frag = P rows, B-frag = V^T rows (d) via ldmatrix
#pragma unroll
        for (int kk = 0; kk < 8; kk++) {
            int jc0 = kk << 3;
            uint32_t af[4], bp[4][4];
            ldsm_x4(af, Ps + ((w << 4) + a_radd + llr) * 68 + jc0 + a_kadd);
#pragma unroll
            for (int p = 0; p < 4; p++)
                ldsm_x4(bp[p], Vs + ((p << 4) + b_nadd + llr) * 68 + jc0 + b_kadd);
#pragma unroll
            for (int dt = 0; dt < 8; dt++)
                mma8(oacc[dt], af, &bp[dt >> 1][(dt & 1) << 1]);
        }
        __syncthreads();
    }

    float inv0 = 1.0f / lh[0], inv1 = 1.0f / lh[1];
    float* o1 = out + (rowbase + i0 + r0l) * kD + h * 64;
    float* o2 = out + (rowbase + i0 + r0l + 8) * kD + h * 64;
#pragma unroll
    for (int dt = 0; dt < 8; dt++) {
        int dc = (dt << 3) + (quad << 1);
        *(float2*)(o1 + dc) = make_float2(tfr(oacc[dt][0] * inv0), tfr(oacc[dt][1] * inv0));
        *(float2*)(o2 + dc) = make_float2(tfr(oacc[dt][2] * inv1), tfr(oacc[dt][3] * inv1));
    }
}

// ---------------- LN(a + r): writes full + rounded copies ----------------
__global__ __launch_bounds__(256) void ln_residual_dual(
    const float* __restrict__ a, const float* __restrict__ r,
    const float* __restrict__ g, const float* __restrict__ bet,
    float* __restrict__ outf, float* __restrict__ outr)
{
    const size_t row = (size_t)blockIdx.x * 8 + (threadIdx.x >> 5);
    const int lane = threadIdx.x & 31;
    const float* ap = a + row * kD;
    const float* rp = r + row * kD;
    float v[16];
    float sum = 0.0f;
#pragma unroll
    for (int t = 0; t < 16; t++) {
        v[t] = ap[lane + t * 32] + rp[lane + t * 32];
        sum += v[t];
    }
#pragma unroll
    for (int s = 16; s; s >>= 1) sum += __shfl_xor_sync(0xffffffffu, sum, s);
    float mean = sum * (1.0f / kD);
    float s2 = 0.0f;
#pragma unroll
    for (int t = 0; t < 16; t++) { float d = v[t] - mean; s2 += d * d; }
#pragma unroll
    for (int s = 16; s; s >>= 1) s2 += __shfl_xor_sync(0xffffffffu, s2, s);
    float rstd = rsqrtf(s2 * (1.0f / kD) + 1e-5f);
#pragma unroll
    for (int t = 0; t < 16; t++) {
        int c = lane + t * 32;
        float o = (v[t] - mean) * rstd * g[c] + bet[c];
        outf[row * kD + c] = o;
        outr[row * kD + c] = tfr(o);
    }
}

// ---------------- final logits ----------------
__global__ __launch_bounds__(256) void logits_kernel(
    const float* __restrict__ x, const float* __restrict__ w,
    float* __restrict__ out)
{
    int gw = (blockIdx.x * blockDim.x + threadIdx.x) >> 5;
    int lane = threadIdx.x & 31;
    if (gw >= kB * kVOCAB) return;
    int b = gw >> 10;
    int vcb = gw & (kVOCAB - 1);
    const float* xr = x + ((size_t)b * kS + (kS - 1)) * kD;
    const float* wr = w + (size_t)vcb * kD;
    float s = 0.0f;
#pragma unroll
    for (int t = 0; t < 16; t++) s += xr[lane + t * 32] * wr[lane + t * 32];
#pragma unroll
    for (int sh = 16; sh; sh >>= 1) s += __shfl_xor_sync(0xffffffffu, s, sh);
    if (lane == 0) out[gw] = s;
}

// ---------------- host launcher ----------------
extern "C" void kernel_launch(void* const* d_in, const int* in_sizes, int n_in,
                              void* d_out, int out_size)
{
    (void)in_sizes; (void)n_in; (void)out_size;
    const int*   raw_x = (const int*)d_in[0];
    const int*   deg   = (const int*)d_in[1];
    const int*   pci   = (const int*)d_in[2];
    const int*   pcn   = (const int*)d_in[3];
    const int*   sbi   = (const int*)d_in[4];
    const int*   sbn   = (const int*)d_in[5];
    const float* vemb  = (const float*)d_in[6];
    const float* demb  = (const float*)d_in[7];
    const float* are   = (const float*)d_in[8];
    const float* rel   = (const float*)d_in[9];
    const float* Wq    = (const float*)d_in[10];
    const float* bq    = (const float*)d_in[11];
    const float* Wk    = (const float*)d_in[12];
    const float* bk    = (const float*)d_in[13];
    const float* Wv    = (const float*)d_in[14];
    const float* bv    = (const float*)d_in[15];
    const float* Wo    = (const float*)d_in[16];
    const float* bo    = (const float*)d_in[17];
    const float* W1    = (const float*)d_in[18];
    const float* b1    = (const float*)d_in[19];
    const float* W2    = (const float*)d_in[20];
    const float* b2    = (const float*)d_in[21];
    const float* lng   = (const float*)d_in[22];
    const float* lnb   = (const float*)d_in[23];
    const float* logw  = (const float*)d_in[24];
    float* out = (float*)d_out;

    float *x, *xr, *qkv, *vt, *att, *t, *ff, *bias;
    float *wqkv, *bqkv, *wo, *w1, *w2;
    cudaGetSymbolAddress((void**)&x,    g_x);
    cudaGetSymbolAddress((void**)&xr,   g_xr);
    cudaGetSymbolAddress((void**)&qkv,  g_qkv);
    cudaGetSymbolAddress((void**)&vt,   g_vt);
    cudaGetSymbolAddress((void**)&att,  g_att);
    cudaGetSymbolAddress((void**)&t,    g_t);
    cudaGetSymbolAddress((void**)&ff,   g_ff);
    cudaGetSymbolAddress((void**)&bias, g_bias);
    cudaGetSymbolAddress((void**)&wqkv, g_wqkv);
    cudaGetSymbolAddress((void**)&bqkv, g_bqkv);
    cudaGetSymbolAddress((void**)&wo,   g_wo);
    cudaGetSymbolAddress((void**)&w1,   g_w1);
    cudaGetSymbolAddress((void**)&w2,   g_w2);

    const int flashSmem = kFlashSmemFl * sizeof(float);      // 87,040
    cudaFuncSetAttribute(gemm_tc<false, true, 1>,  cudaFuncAttributeMaxDynamicSharedMemorySize, kGemmSmemBytes);
    cudaFuncSetAttribute(gemm_tc<false, false, 0>, cudaFuncAttributeMaxDynamicSharedMemorySize, kGemmSmemBytes);
    cudaFuncSetAttribute(gemm_tc<true, true, 0>,   cudaFuncAttributeMaxDynamicSharedMemorySize, kGemmSmemBytes);
    cudaFuncSetAttribute(flash_attn,               cudaFuncAttributeMaxDynamicSharedMemorySize, flashSmem);

    // ---- prep (cheap, once per replay) ----
    prep_qkv_w<<<2048, 256>>>(Wq, Wk, Wv, wqkv);
    prep_qkv_b<<<(kL * kQKVN + 255) / 256, 256>>>(bq, bk, bv, bqkv);
    round_copy<<<2048, 256>>>(Wo, wo, (size_t)kL * kD * kD);
    round_copy<<<2048, 256>>>(W1, w1, (size_t)kL * kDFF * kD);
    round_copy<<<2048, 256>>>(W2, w2, (size_t)kL * kD * kDFF);
    zero_bias<<<2048, 256>>>(bias);
    scatter_pc<<<(kNPC + 255) / 256, 256>>>(pci, rel, bias);
    scatter_sib<<<(kNS + 255) / 256, 256>>>(sbi, rel, bias);

    embed_kernel<<<kM, 128>>>(raw_x, deg, vemb, demb, x);
    relnow_kernel<<<(kB * kD + 255) / 256, 256>>>(pcn, sbn, are, x);
    round_copy<<<2048, 256>>>(x, xr, (size_t)kM * kD);

    const dim3 gQKV(kQKVN / 128, kM / 128);  // (12, 64)
    const dim3 gD(kD / 128, kM / 128);       // (4, 64)
    const dim3 gFF(kDFF / 128, kM / 128);    // (16, 64)
    const dim3 gFl(kS / 128, kB * kH);       // (4, 128)

    for (int l = 0; l < kL; l++) {
        const float* wqkvl = wqkv + (size_t)l * kQKVN * kD;
        const float* bqkvl = bqkv + (size_t)l * kQKVN;
        const float* wol = wo + (size_t)l * kD * kD;
        const float* w1l = w1 + (size_t)l * kDFF * kD;
        const float* w2l = w2 + (size_t)l * kD * kDFF;
        const float* bol = bo + (size_t)l * kD;
        const float* b1l = b1 + (size_t)l * kDFF;
        const float* b2l = b2 + (size_t)l * kD;
        const float* lngl = lng + (size_t)l * kD;
        const float* lnbl = lnb + (size_t)l * kD;

        gemm_tc<false, true, 1><<<gQKV, 256, kGemmSmemBytes>>>(xr, wqkvl, bqkvl, qkv, vt, kM, kQKVN, kD);
        flash_attn<<<gFl, 256, flashSmem>>>(qkv, vt, bias, att);
        gemm_tc<false, false, 0><<<gD, 256, kGemmSmemBytes>>>(att, wol, bol, t, nullptr, kM, kD, kD);
        ln_residual_dual<<<kM / 8, 256>>>(x, t, lngl, lnbl, x, xr);

        gemm_tc<true, true, 0><<<gFF, 256, kGemmSmemBytes>>>(xr, w1l, b1l, ff, nullptr, kM, kDFF, kD);
        gemm_tc<false, false, 0><<<gD, 256, kGemmSmemBytes>>>(ff, w2l, b2l, t, nullptr, kM, kD, kDFF);
        ln_residual_dual<<<kM / 8, 256>>>(x, t, lngl, lnbl, x, xr);
    }

    logits_kernel<<<(kB * kVOCAB * 32 + 255) / 256, 256>>>(x, logw, out);
}

// round 7
// speedup vs baseline: 7.1669x; 1.7027x over previous
#include <cuda_runtime.h>
#include <cuda_fp16.h>
#include <math.h>
#include <stdint.h>

// ---------------- problem constants ----------------
constexpr int kB = 16;
constexpr int kS = 512;
constexpr int kD = 512;
constexpr int kH = 8;
constexpr int kL = 6;
constexpr int kDFF = 2048;
constexpr int kVOCAB = 1024;
constexpr int kNPC = 4096;
constexpr int kNS = 4096;
constexpr int kM = kB * kS;  // 8192 rows
constexpr int kQKVN = 3 * kD; // 1536

// ---------------- scratch (static device globals; no allocations) ----------------
__device__ float  g_x[(size_t)kM * kD];        // residual stream (fp32)
__device__ __half g_xh[(size_t)kM * kD];       // half copy for GEMM input
__device__ __half g_qkvh[(size_t)kM * 1024];   // Q (0-511) and K (512-1023), half
__device__ __half g_vth[(size_t)kM * kD];      // V transposed: [b][h*64+d][s], half
__device__ __half g_atth[(size_t)kM * kD];     // attention output, half
__device__ float  g_t[(size_t)kM * kD];        // pre-LN branch (fp32)
__device__ __half g_ffh[(size_t)kM * kDFF];    // FFN hidden, half
__device__ float  g_bias[(size_t)kB * kS * kS];// dense relation bias (fp32)
__device__ __half g_wqkvh[(size_t)kL * kQKVN * kD];
__device__ float  g_bqkv[(size_t)kL * kQKVN];
__device__ __half g_woh[(size_t)kL * kD * kD];
__device__ __half g_w1h[(size_t)kL * kDFF * kD];
__device__ __half g_w2h[(size_t)kL * kD * kDFF];

// ---------------- mma / ldmatrix / cp.async helpers ----------------
__device__ __forceinline__ void mma16(float* c, const uint32_t* a, const uint32_t* b) {
    asm volatile(
        "mma.sync.aligned.m16n8k16.row.col.f32.f16.f16.f32 "
        "{%0,%1,%2,%3},{%4,%5,%6,%7},{%8,%9},{%0,%1,%2,%3};"
        : "+f"(c[0]), "+f"(c[1]), "+f"(c[2]), "+f"(c[3])
        : "r"(a[0]), "r"(a[1]), "r"(a[2]), "r"(a[3]), "r"(b[0]), "r"(b[1]));
}

__device__ __forceinline__ void ldsm_x4h(uint32_t* r, const __half* p) {
    uint32_t addr = (uint32_t)__cvta_generic_to_shared(p);
    asm volatile("ldmatrix.sync.aligned.m8n8.x4.shared.b16 {%0,%1,%2,%3}, [%4];"
        : "=r"(r[0]), "=r"(r[1]), "=r"(r[2]), "=r"(r[3]) : "r"(addr));
}

__device__ __forceinline__ void cpa16(void* smem_dst, const void* gsrc) {
    uint32_t sa = (uint32_t)__cvta_generic_to_shared(smem_dst);
    asm volatile("cp.async.cg.shared.global [%0], [%1], 16;" :: "r"(sa), "l"(gsrc) : "memory");
}
__device__ __forceinline__ void cpa_commit() {
    asm volatile("cp.async.commit_group;" ::: "memory");
}
__device__ __forceinline__ void cpa_wait0() {
    asm volatile("cp.async.wait_group 0;" ::: "memory");
}
__device__ __forceinline__ void cpa_wait1() {
    asm volatile("cp.async.wait_group 1;" ::: "memory");
}

// ---------------- prep kernels ----------------
__global__ __launch_bounds__(256) void prep_qkv_w(
    const float* __restrict__ Wq, const float* __restrict__ Wk,
    const float* __restrict__ Wv, __half* __restrict__ wout)
{
    size_t n = (size_t)kL * kQKVN * kD;
    for (size_t idx = (size_t)blockIdx.x * blockDim.x + threadIdx.x; idx < n;
         idx += (size_t)gridDim.x * blockDim.x) {
        size_t l = idx / ((size_t)kQKVN * kD);
        size_t rem = idx % ((size_t)kQKVN * kD);
        int r = (int)(rem / kD), c = (int)(rem % kD);
        float v;
        if (r < kD)            v = Wq[(l * kD + r) * kD + c];
        else if (r < 2 * kD)   v = Wk[(l * kD + (r - kD)) * kD + c];
        else                   v = Wv[(l * kD + (r - 2 * kD)) * kD + c];
        wout[idx] = __float2half_rn(v);
    }
}

__global__ __launch_bounds__(256) void prep_qkv_b(
    const float* __restrict__ bq, const float* __restrict__ bk,
    const float* __restrict__ bv, float* __restrict__ bout)
{
    int idx = blockIdx.x * blockDim.x + threadIdx.x;
    if (idx >= kL * kQKVN) return;
    int l = idx / kQKVN, r = idx % kQKVN;
    float v;
    if (r < kD)          v = bq[l * kD + r];
    else if (r < 2 * kD) v = bk[l * kD + (r - kD)];
    else                 v = bv[l * kD + (r - 2 * kD)];
    bout[idx] = v;
}

__global__ __launch_bounds__(256) void half_copy(
    const float* __restrict__ src, __half* __restrict__ dst, size_t n)
{
    for (size_t i = (size_t)blockIdx.x * blockDim.x + threadIdx.x; i < n;
         i += (size_t)gridDim.x * blockDim.x)
        dst[i] = __float2half_rn(src[i]);
}

// ---------------- dense relation-bias matrix ----------------
__global__ __launch_bounds__(256) void zero_bias(float* __restrict__ bias)
{
    size_t n = (size_t)kB * kS * kS;
    for (size_t i = (size_t)blockIdx.x * blockDim.x + threadIdx.x; i < n;
         i += (size_t)gridDim.x * blockDim.x)
        bias[i] = 0.0f;
}

__global__ __launch_bounds__(256) void scatter_pc(
    const int* __restrict__ pci, const float* __restrict__ rel, float* __restrict__ bias)
{
    int e = blockIdx.x * blockDim.x + threadIdx.x;
    if (e >= kNPC) return;
    int b = pci[e * 3 + 0], i = pci[e * 3 + 1], j = pci[e * 3 + 2];
    atomicAdd(&bias[((size_t)b * kS + i) * kS + j], rel[0]);
    atomicAdd(&bias[((size_t)b * kS + j) * kS + i], rel[1]);
}

__global__ __launch_bounds__(256) void scatter_sib(
    const int* __restrict__ sbi, const float* __restrict__ rel, float* __restrict__ bias)
{
    int e = blockIdx.x * blockDim.x + threadIdx.x;
    if (e >= kNS) return;
    int b = sbi[e * 3 + 0], i = sbi[e * 3 + 1], j = sbi[e * 3 + 2];
    float r2 = rel[2];
    atomicAdd(&bias[((size_t)b * kS + i) * kS + j], r2);
    atomicAdd(&bias[((size_t)b * kS + j) * kS + i], r2);
}

// ---------------- embedding + positional + degree ----------------
__global__ __launch_bounds__(128) void embed_kernel(
    const int* __restrict__ raw_x, const int* __restrict__ deg,
    const float* __restrict__ vemb, const float* __restrict__ demb,
    float* __restrict__ x)
{
    const int row = blockIdx.x;
    const int s = row & (kS - 1);
    const int tok = raw_x[row];
    const int dg = deg[row];
    const float c0 = -logf(10000.0f) / (float)kD;
    for (int c = threadIdx.x; c < kD; c += blockDim.x) {
        int p = c >> 1;
        float ang = (float)s * expf((float)(2 * p) * c0);
        float pe = (c & 1) ? cosf(ang) : sinf(ang);
        x[(size_t)row * kD + c] = vemb[(size_t)tok * kD + c] + pe + demb[(size_t)dg * kD + c];
    }
}

__global__ __launch_bounds__(256) void relnow_kernel(
    const int* __restrict__ pcn, const int* __restrict__ sn,
    const float* __restrict__ are, float* __restrict__ x)
{
    int idx = blockIdx.x * blockDim.x + threadIdx.x;
    if (idx >= kB * kD) return;
    int b = idx / kD, c = idx % kD;
    {
        int bb = pcn[b * 2 + 0], ss = pcn[b * 2 + 1];
        atomicAdd(&x[((size_t)bb * kS + ss) * kD + c], are[c]);
    }
    {
        int bb = sn[b * 2 + 0], ss = sn[b * 2 + 1];
        atomicAdd(&x[((size_t)bb * kS + ss) * kD + c], are[kD + c]);
    }
}

// ============================================================
// fp16 tensor-core GEMM, 3-stage cp.async pipeline.
// acc(fp32) = A[M,K](half) @ W[N,K]^T(half) + bias(fp32)
// MODE 0: fp32 out Cf.  MODE 1: half out Ch (+optional relu).
// MODE 2: QKV — Q,K tiles (n0<1024) to Ch stride 1024; V tiles
//         (n0>=1024) transposed into vt[b][hd][s] (half).
// 128x128 tile, 8 warps (64x32), BK=64 halfs, smem stride 72.
// ============================================================
constexpr int kStrideH = 72;
constexpr int kStageH = 2 * 128 * kStrideH;            // halfs per stage (A+B)
constexpr int kGemmSmemBytes = 3 * kStageH * 2;        // 110,592 B

template <bool RELU, int MODE>
__global__ __launch_bounds__(256, 2) void gemm_fp16(
    const __half* __restrict__ A, const __half* __restrict__ W,
    const float* __restrict__ bias, float* __restrict__ Cf,
    __half* __restrict__ Ch, __half* __restrict__ vt,
    int M, int N, int K)
{
    extern __shared__ __half smh[];
    const int tid = threadIdx.x;
    const int lane = tid & 31, warp = tid >> 5;
    const int wm = warp >> 2, wn = warp & 3;
    const int m0 = blockIdx.y << 7, n0 = blockIdx.x << 7;

    // fragment lane addressing
    const int a_row = (((lane >> 3) & 1) << 3) + (lane & 7);
    const int a_col = (lane >> 4) << 3;
    const int b_row = ((lane >> 4) << 3) + (lane & 7);
    const int b_col = ((lane >> 3) & 1) << 3;

    auto issue = [&](int ch, int st) {
        const __half* Ab = A + (size_t)m0 * K + (size_t)ch * 64;
        const __half* Wb = W + (size_t)n0 * K + (size_t)ch * 64;
        __half* Ad = smh + st * kStageH;
        __half* Bd = Ad + (kStageH >> 1);
#pragma unroll
        for (int it = 0; it < 4; it++) {
            int u = tid + (it << 8);       // 0..1023
            int row = u >> 3, c8 = (u & 7) << 3;
            cpa16(Ad + row * kStrideH + c8, Ab + (size_t)row * K + c8);
            cpa16(Bd + row * kStrideH + c8, Wb + (size_t)row * K + c8);
        }
        cpa_commit();
    };

    float acc[4][4][4] = {};
    const int nch = K >> 6;
    issue(0, 0);
    issue(1, 1);
    int st = 0, st2 = 2;
    for (int ch = 0; ch < nch; ch++) {
        if (ch + 1 < nch) cpa_wait1(); else cpa_wait0();
        __syncthreads();
        if (ch + 2 < nch) issue(ch + 2, st2);
        const __half* Ar = smh + st * kStageH;
        const __half* Br = Ar + (kStageH >> 1);
#pragma unroll
        for (int ks = 0; ks < 4; ks++) {
            int kc = ks << 4;
            uint32_t af[4][4], bp[2][4];
#pragma unroll
            for (int mt = 0; mt < 4; mt++)
                ldsm_x4h(af[mt], Ar + ((wm << 6) + (mt << 4) + a_row) * kStrideH + kc + a_col);
#pragma unroll
            for (int p = 0; p < 2; p++)
                ldsm_x4h(bp[p], Br + ((wn << 5) + (p << 4) + b_row) * kStrideH + kc + b_col);
#pragma unroll
            for (int mt = 0; mt < 4; mt++)
#pragma unroll
                for (int nt = 0; nt < 4; nt++)
                    mma16(acc[mt][nt], af[mt], &bp[nt >> 1][(nt & 1) << 1]);
        }
        st = (st == 2) ? 0 : st + 1;
        st2 = (st2 == 2) ? 0 : st2 + 1;
    }

    if (MODE == 2 && n0 >= 1024) {
        // V tile -> vt[b][hd][s] transposed (half)
        const int bidx = m0 >> 9;
        __half* vtb = vt + ((size_t)bidx << 9) * kS;
#pragma unroll
        for (int mt = 0; mt < 4; mt++) {
            int s = (m0 & 511) + (wm << 6) + (mt << 4) + (lane >> 2);
#pragma unroll
            for (int nt = 0; nt < 4; nt++) {
                int col = n0 + (wn << 5) + (nt << 3) + ((lane & 3) << 1);
                int hd = col - 1024;
                float bb0 = bias[col], bb1 = bias[col + 1];
                vtb[(size_t)hd * kS + s]           = __float2half_rn(acc[mt][nt][0] + bb0);
                vtb[(size_t)(hd + 1) * kS + s]     = __float2half_rn(acc[mt][nt][1] + bb1);
                vtb[(size_t)hd * kS + s + 8]       = __float2half_rn(acc[mt][nt][2] + bb0);
                vtb[(size_t)(hd + 1) * kS + s + 8] = __float2half_rn(acc[mt][nt][3] + bb1);
            }
        }
        return;
    }
#pragma unroll
    for (int mt = 0; mt < 4; mt++) {
        int row = m0 + (wm << 6) + (mt << 4) + (lane >> 2);
#pragma unroll
        for (int nt = 0; nt < 4; nt++) {
            int col = n0 + (wn << 5) + (nt << 3) + ((lane & 3) << 1);
            float bb0 = bias[col], bb1 = bias[col + 1];
            float v0 = acc[mt][nt][0] + bb0, v1 = acc[mt][nt][1] + bb1;
            float v2 = acc[mt][nt][2] + bb0, v3 = acc[mt][nt][3] + bb1;
            if (RELU) {
                v0 = fmaxf(v0, 0.0f); v1 = fmaxf(v1, 0.0f);
                v2 = fmaxf(v2, 0.0f); v3 = fmaxf(v3, 0.0f);
            }
            if (MODE == 0) {
                *(float2*)(Cf + (size_t)row * N + col) = make_float2(v0, v1);
                *(float2*)(Cf + (size_t)(row + 8) * N + col) = make_float2(v2, v3);
            } else if (MODE == 1) {
                *(__half2*)(Ch + (size_t)row * N + col) = __floats2half2_rn(v0, v1);
                *(__half2*)(Ch + (size_t)(row + 8) * N + col) = __floats2half2_rn(v2, v3);
            } else {
                // MODE 2, Q/K tile: stride 1024
                *(__half2*)(Ch + (size_t)row * 1024 + col) = __floats2half2_rn(v0, v1);
                *(__half2*)(Ch + (size_t)(row + 8) * 1024 + col) = __floats2half2_rn(v2, v3);
            }
        }
    }
}

// ============================================================
// Fused fp16 flash attention with additive dense fp32 bias.
// Q,K from qkvh [kM][1024]; V from vth [b][h*64+d][s].
// ============================================================
constexpr int kQsOff = 0;                        // [128][72]
constexpr int kKsOff = 128 * kStrideH;           // [64][72]
constexpr int kVsOff = kKsOff + 64 * kStrideH;   // [64][72]
constexpr int kPsOff = kVsOff + 64 * kStrideH;   // [128][72]
constexpr int kFlashSmemH = kPsOff + 128 * kStrideH;
constexpr int kFlashSmemBytes = kFlashSmemH * 2; // 55,296 B

__global__ __launch_bounds__(256, 2) void flash_attn(
    const __half* __restrict__ qkv, const __half* __restrict__ vt,
    const float* __restrict__ bias, __half* __restrict__ out)
{
    extern __shared__ __half smh[];
    __half* Qs = smh + kQsOff;
    __half* Ks = smh + kKsOff;
    __half* Vs = smh + kVsOff;
    __half* Ps = smh + kPsOff;
    const int bh = blockIdx.y;
    const int b = bh >> 3, h = bh & 7;
    const int i0 = blockIdx.x << 7;
    const int tid = threadIdx.x;
    const int lane = tid & 31, w = tid >> 5;
    const int quad = lane & 3;
    const int r0l = (w << 4) + (lane >> 2);
    const size_t rowbase = (size_t)b * kS;

    const int a_row = (((lane >> 3) & 1) << 3) + (lane & 7);
    const int a_col = (lane >> 4) << 3;
    const int b_row = ((lane >> 4) << 3) + (lane & 7);
    const int b_col = ((lane >> 3) & 1) << 3;

    // load Q tile (128 x 64 halfs)
    {
        const __half* Qg = qkv + (rowbase + i0) * 1024 + h * 64;
#pragma unroll
        for (int it = 0; it < 4; it++) {
            int u = tid + (it << 8);
            int row = u >> 3, c8 = (u & 7) << 3;
            cpa16(Qs + row * kStrideH + c8, Qg + (size_t)row * 1024 + c8);
        }
        cpa_commit();
    }

    float oacc[8][4] = {};
    float mh[2] = {-1e30f, -1e30f};
    float lh[2] = {0.0f, 0.0f};

    const __half* Vgb = vt + ((rowbase << 9) + (size_t)h * 64 * kS);

    for (int jt = 0; jt < 8; jt++) {
        const int j0 = jt << 6;
        {
            const __half* Kg = qkv + (rowbase + j0) * 1024 + 512 + h * 64;
#pragma unroll
            for (int it = 0; it < 2; it++) {
                int u = tid + (it << 8);
                int row = u >> 3, c8 = (u & 7) << 3;
                cpa16(Ks + row * kStrideH + c8, Kg + (size_t)row * 1024 + c8);
                cpa16(Vs + row * kStrideH + c8, Vgb + (size_t)row * kS + j0 + c8);
            }
            cpa_commit();
        }
        cpa_wait0();
        __syncthreads();

        // S = Q @ K^T   (warp: 16 rows x 64 j)
        float s[8][4] = {};
#pragma unroll
        for (int ks = 0; ks < 4; ks++) {
            int kc = ks << 4;
            uint32_t af[4], bp[4][4];
            ldsm_x4h(af, Qs + ((w << 4) + a_row) * kStrideH + kc + a_col);
#pragma unroll
            for (int p = 0; p < 4; p++)
                ldsm_x4h(bp[p], Ks + ((p << 4) + b_row) * kStrideH + kc + b_col);
#pragma unroll
            for (int nt = 0; nt < 8; nt++)
                mma16(s[nt], af, &bp[nt >> 1][(nt & 1) << 1]);
        }

        const size_t bi1 = (rowbase + i0 + r0l) * kS + j0;
        const size_t bi2 = (rowbase + i0 + r0l + 8) * kS + j0;
#pragma unroll
        for (int nt = 0; nt < 8; nt++) {
            int jc = (nt << 3) + (quad << 1);
            float2 z1 = *(const float2*)(bias + bi1 + jc);
            float2 z2 = *(const float2*)(bias + bi2 + jc);
            s[nt][0] = s[nt][0] * 0.125f + z1.x;
            s[nt][1] = s[nt][1] * 0.125f + z1.y;
            s[nt][2] = s[nt][2] * 0.125f + z2.x;
            s[nt][3] = s[nt][3] * 0.125f + z2.y;
        }
        float mx0 = -1e30f, mx1 = -1e30f;
#pragma unroll
        for (int nt = 0; nt < 8; nt++) {
            mx0 = fmaxf(mx0, fmaxf(s[nt][0], s[nt][1]));
            mx1 = fmaxf(mx1, fmaxf(s[nt][2], s[nt][3]));
        }
        mx0 = fmaxf(mx0, __shfl_xor_sync(0xffffffffu, mx0, 1));
        mx0 = fmaxf(mx0, __shfl_xor_sync(0xffffffffu, mx0, 2));
        mx1 = fmaxf(mx1, __shfl_xor_sync(0xffffffffu, mx1, 1));
        mx1 = fmaxf(mx1, __shfl_xor_sync(0xffffffffu, mx1, 2));
        float mn0 = fmaxf(mh[0], mx0), mn1 = fmaxf(mh[1], mx1);
        float sc0 = __expf(mh[0] - mn0), sc1 = __expf(mh[1] - mn1);
        mh[0] = mn0; mh[1] = mn1;
        float ps0 = 0.0f, ps1 = 0.0f;
#pragma unroll
        for (int nt = 0; nt < 8; nt++) {
            __half2 h1 = __floats2half2_rn(__expf(s[nt][0] - mn0), __expf(s[nt][1] - mn0));
            __half2 h2 = __floats2half2_rn(__expf(s[nt][2] - mn1), __expf(s[nt][3] - mn1));
            float2 f1 = __half22float2(h1);
            float2 f2 = __half22float2(h2);
            ps0 += f1.x + f1.y; ps1 += f2.x + f2.y;
            int jc = (nt << 3) + (quad << 1);
            *(__half2*)(Ps + r0l * kStrideH + jc) = h1;
            *(__half2*)(Ps + (r0l + 8) * kStrideH + jc) = h2;
        }
        ps0 += __shfl_xor_sync(0xffffffffu, ps0, 1);
        ps0 += __shfl_xor_sync(0xffffffffu, ps0, 2);
        ps1 += __shfl_xor_sync(0xffffffffu, ps1, 1);
        ps1 += __shfl_xor_sync(0xffffffffu, ps1, 2);
        lh[0] = lh[0] * sc0 + ps0;
        lh[1] = lh[1] * sc1 + ps1;
#pragma unroll
        for (int dt = 0; dt < 8; dt++) {
            oacc[dt][0] *= sc0; oacc[dt][1] *= sc0;
            oacc[dt][2] *= sc1; oacc[dt][3] *= sc1;
        }
        __syncwarp();

        // O += P @ V   (A = warp-local P rows; B = V^T rows d)
#pragma unroll
        for (int ks = 0; ks < 4; ks++) {
            int kc = ks << 4;
            uint32_t af[4], bp[4][4];
            ldsm_x4h(af, Ps + ((w << 4) + a_row) * kStrideH + kc + a_col);
#pragma unroll
            for (int p = 0; p < 4; p++)
                ldsm_x4h(bp[p], Vs + ((p << 4) + b_row) * kStrideH + kc + b_col);
#pragma unroll
            for (int dt = 0; dt < 8; dt++)
                mma16(oacc[dt], af, &bp[dt >> 1][(dt & 1) << 1]);
        }
        __syncthreads();   // Ks/Vs consumed by all warps before next load
    }

    float inv0 = 1.0f / lh[0], inv1 = 1.0f / lh[1];
    __half* o1 = out + (rowbase + i0 + r0l) * kD + h * 64;
    __half* o2 = out + (rowbase + i0 + r0l + 8) * kD + h * 64;
#pragma unroll
    for (int dt = 0; dt < 8; dt++) {
        int dc = (dt << 3) + (quad << 1);
        *(__half2*)(o1 + dc) = __floats2half2_rn(oacc[dt][0] * inv0, oacc[dt][1] * inv0);
        *(__half2*)(o2 + dc) = __floats2half2_rn(oacc[dt][2] * inv1, oacc[dt][3] * inv1);
    }
}

// ---------------- LN(a + r): writes fp32 + half copies ----------------
__global__ __launch_bounds__(256) void ln_residual_dual(
    const float* __restrict__ a, const float* __restrict__ r,
    const float* __restrict__ g, const float* __restrict__ bet,
    float* __restrict__ outf, __half* __restrict__ outh)
{
    const size_t row = (size_t)blockIdx.x * 8 + (threadIdx.x >> 5);
    const int lane = threadIdx.x & 31;
    const float* ap = a + row * kD;
    const float* rp = r + row * kD;
    float v[16];
    float sum = 0.0f;
#pragma unroll
    for (int t = 0; t < 16; t++) {
        v[t] = ap[lane + t * 32] + rp[lane + t * 32];
        sum += v[t];
    }
#pragma unroll
    for (int s = 16; s; s >>= 1) sum += __shfl_xor_sync(0xffffffffu, sum, s);
    float mean = sum * (1.0f / kD);
    float s2 = 0.0f;
#pragma unroll
    for (int t = 0; t < 16; t++) { float d = v[t] - mean; s2 += d * d; }
#pragma unroll
    for (int s = 16; s; s >>= 1) s2 += __shfl_xor_sync(0xffffffffu, s2, s);
    float rstd = rsqrtf(s2 * (1.0f / kD) + 1e-5f);
#pragma unroll
    for (int t = 0; t < 16; t++) {
        int c = lane + t * 32;
        float o = (v[t] - mean) * rstd * g[c] + bet[c];
        outf[row * kD + c] = o;
        outh[row * kD + c] = __float2half_rn(o);
    }
}

// ---------------- final logits (fp32) ----------------
__global__ __launch_bounds__(256) void logits_kernel(
    const float* __restrict__ x, const float* __restrict__ w,
    float* __restrict__ out)
{
    int gw = (blockIdx.x * blockDim.x + threadIdx.x) >> 5;
    int lane = threadIdx.x & 31;
    if (gw >= kB * kVOCAB) return;
    int b = gw >> 10;
    int vcb = gw & (kVOCAB - 1);
    const float* xr = x + ((size_t)b * kS + (kS - 1)) * kD;
    const float* wr = w + (size_t)vcb * kD;
    float s = 0.0f;
#pragma unroll
    for (int t = 0; t < 16; t++) s += xr[lane + t * 32] * wr[lane + t * 32];
#pragma unroll
    for (int sh = 16; sh; sh >>= 1) s += __shfl_xor_sync(0xffffffffu, s, sh);
    if (lane == 0) out[gw] = s;
}

// ---------------- host launcher ----------------
extern "C" void kernel_launch(void* const* d_in, const int* in_sizes, int n_in,
                              void* d_out, int out_size)
{
    (void)in_sizes; (void)n_in; (void)out_size;
    const int*   raw_x = (const int*)d_in[0];
    const int*   deg   = (const int*)d_in[1];
    const int*   pci   = (const int*)d_in[2];
    const int*   pcn   = (const int*)d_in[3];
    const int*   sbi   = (const int*)d_in[4];
    const int*   sbn   = (const int*)d_in[5];
    const float* vemb  = (const float*)d_in[6];
    const float* demb  = (const float*)d_in[7];
    const float* are   = (const float*)d_in[8];
    const float* rel   = (const float*)d_in[9];
    const float* Wq    = (const float*)d_in[10];
    const float* bq    = (const float*)d_in[11];
    const float* Wk    = (const float*)d_in[12];
    const float* bk    = (const float*)d_in[13];
    const float* Wv    = (const float*)d_in[14];
    const float* bv    = (const float*)d_in[15];
    const float* Wo    = (const float*)d_in[16];
    const float* bo    = (const float*)d_in[17];
    const float* W1    = (const float*)d_in[18];
    const float* b1    = (const float*)d_in[19];
    const float* W2    = (const float*)d_in[20];
    const float* b2    = (const float*)d_in[21];
    const float* lng   = (const float*)d_in[22];
    const float* lnb   = (const float*)d_in[23];
    const float* logw  = (const float*)d_in[24];
    float* out = (float*)d_out;

    float *x, *t, *bias, *bqkv;
    __half *xh, *qkvh, *vth, *atth, *ffh, *wqkvh, *woh, *w1h, *w2h;
    cudaGetSymbolAddress((void**)&x,     g_x);
    cudaGetSymbolAddress((void**)&xh,    g_xh);
    cudaGetSymbolAddress((void**)&qkvh,  g_qkvh);
    cudaGetSymbolAddress((void**)&vth,   g_vth);
    cudaGetSymbolAddress((void**)&atth,  g_atth);
    cudaGetSymbolAddress((void**)&t,     g_t);
    cudaGetSymbolAddress((void**)&ffh,   g_ffh);
    cudaGetSymbolAddress((void**)&bias,  g_bias);
    cudaGetSymbolAddress((void**)&wqkvh, g_wqkvh);
    cudaGetSymbolAddress((void**)&bqkv,  g_bqkv);
    cudaGetSymbolAddress((void**)&woh,   g_woh);
    cudaGetSymbolAddress((void**)&w1h,   g_w1h);
    cudaGetSymbolAddress((void**)&w2h,   g_w2h);

    cudaFuncSetAttribute(gemm_fp16<false, 2>, cudaFuncAttributeMaxDynamicSharedMemorySize, kGemmSmemBytes);
    cudaFuncSetAttribute(gemm_fp16<false, 0>, cudaFuncAttributeMaxDynamicSharedMemorySize, kGemmSmemBytes);
    cudaFuncSetAttribute(gemm_fp16<true, 1>,  cudaFuncAttributeMaxDynamicSharedMemorySize, kGemmSmemBytes);
    cudaFuncSetAttribute(flash_attn,          cudaFuncAttributeMaxDynamicSharedMemorySize, kFlashSmemBytes);

    // ---- prep ----
    prep_qkv_w<<<2048, 256>>>(Wq, Wk, Wv, wqkvh);
    prep_qkv_b<<<(kL * kQKVN + 255) / 256, 256>>>(bq, bk, bv, bqkv);
    half_copy<<<2048, 256>>>(Wo, woh, (size_t)kL * kD * kD);
    half_copy<<<2048, 256>>>(W1, w1h, (size_t)kL * kDFF * kD);
    half_copy<<<2048, 256>>>(W2, w2h, (size_t)kL * kD * kDFF);
    zero_bias<<<2048, 256>>>(bias);
    scatter_pc<<<(kNPC + 255) / 256, 256>>>(pci, rel, bias);
    scatter_sib<<<(kNS + 255) / 256, 256>>>(sbi, rel, bias);

    embed_kernel<<<kM, 128>>>(raw_x, deg, vemb, demb, x);
    relnow_kernel<<<(kB * kD + 255) / 256, 256>>>(pcn, sbn, are, x);
    half_copy<<<2048, 256>>>(x, xh, (size_t)kM * kD);

    const dim3 gQKV(kQKVN / 128, kM / 128);  // (12, 64)
    const dim3 gD(kD / 128, kM / 128);       // (4, 64)
    const dim3 gFF(kDFF / 128, kM / 128);    // (16, 64)
    const dim3 gFl(kS / 128, kB * kH);       // (4, 128)

    for (int l = 0; l < kL; l++) {
        const __half* wqkvl = wqkvh + (size_t)l * kQKVN * kD;
        const float*  bqkvl = bqkv + (size_t)l * kQKVN;
        const __half* wol = woh + (size_t)l * kD * kD;
        const __half* w1l = w1h + (size_t)l * kDFF * kD;
        const __half* w2l = w2h + (size_t)l * kD * kDFF;
        const float* bol = bo + (size_t)l * kD;
        const float* b1l = b1 + (size_t)l * kDFF;
        const float* b2l = b2 + (size_t)l * kD;
        const float* lngl = lng + (size_t)l * kD;
        const float* lnbl = lnb + (size_t)l * kD;

        gemm_fp16<false, 2><<<gQKV, 256, kGemmSmemBytes>>>(
            xh, wqkvl, bqkvl, nullptr, qkvh, vth, kM, kQKVN, kD);
        flash_attn<<<gFl, 256, kFlashSmemBytes>>>(qkvh, vth, bias, atth);
        gemm_fp16<false, 0><<<gD, 256, kGemmSmemBytes>>>(
            atth, wol, bol, t, nullptr, nullptr, kM, kD, kD);
        ln_residual_dual<<<kM / 8, 256>>>(x, t, lngl, lnbl, x, xh);

        gemm_fp16<true, 1><<<gFF, 256, kGemmSmemBytes>>>(
            xh, w1l, b1l, nullptr, ffh, nullptr, kM, kDFF, kD);
        gemm_fp16<false, 0><<<gD, 256, kGemmSmemBytes>>>(
            ffh, w2l, b2l, t, nullptr, nullptr, kM, kD, kDFF);
        ln_residual_dual<<<kM / 8, 256>>>(x, t, lngl, lnbl, x, xh);
    }

    logits_kernel<<<(kB * kVOCAB * 32 + 255) / 256, 256>>>(x, logw, out);
}